// round 13
// baseline (speedup 1.0000x reference)
#include <cuda_runtime.h>
#include <cuda_bf16.h>
#include <math.h>

#define BB 256
#define NN 1024
#define NSL 8

// ---------------- device-global scratch ----------------
__device__ float g_kT[BB*64*NN];   // [b][d][n]
__device__ float g_v[BB*NN*64];    // [b][n][d]
__device__ float g_logits[BB*NN];

__device__ __forceinline__ float wsum(float v){
  #pragma unroll
  for(int o=16;o;o>>=1) v += __shfl_xor_sync(0xffffffffu, v, o);
  return v;
}
__device__ __forceinline__ float wmax(float v){
  #pragma unroll
  for(int o=16;o;o>>=1) v = fmaxf(v, __shfl_xor_sync(0xffffffffu, v, o));
  return v;
}
__device__ __forceinline__ float sigf(float x){ return 1.f/(1.f+__expf(-x)); }
__device__ __forceinline__ float rcpf(float x){
  float r; asm("rcp.approx.ftz.f32 %0,%1;":"=f"(r):"f"(x)); return r;
}
__device__ __forceinline__ int br3(int p){ return ((p&1)<<2)|(p&2)|((p&4)>>2); }

// multi-value butterfly: warp-reduce 8 values in 9 shuffles; returns sum of value br3(l&7).
__device__ __forceinline__ float mred8(const float* c, int l){
  float r1[4], r2[2], r3;
  #pragma unroll
  for(int i=0;i<4;i++){
    float send=(l&1)? c[i] : c[i+4];
    float t=__shfl_xor_sync(0xffffffffu, send, 1);
    r1[i]=((l&1)? c[i+4] : c[i])+t;
  }
  #pragma unroll
  for(int i=0;i<2;i++){
    float send=(l&2)? r1[i] : r1[i+2];
    float t=__shfl_xor_sync(0xffffffffu, send, 2);
    r2[i]=((l&2)? r1[i+2] : r1[i])+t;
  }
  {
    float send=(l&4)? r2[0] : r2[1];
    float t=__shfl_xor_sync(0xffffffffu, send, 4);
    r3=((l&4)? r2[1] : r2[0])+t;
  }
  r3+=__shfl_xor_sync(0xffffffffu, r3, 8);
  r3+=__shfl_xor_sync(0xffffffffu, r3, 16);
  return r3;
}

// ================= k_prep: LN(inputs), k/v proj, wi logits; k stored TRANSPOSED =================
__global__ void __launch_bounds__(512,3) k_prep(const float* __restrict__ inp,
        const float* __restrict__ lng, const float* __restrict__ lnb,
        const float* __restrict__ Wk, const float* __restrict__ Wv,
        const float* __restrict__ wiw, const float* __restrict__ wib){
  __shared__ float wkT[64*68];
  __shared__ float wvT[64*68];
  __shared__ float xsT[64*68];   // reused as kbuf then vbuf
  int blk=blockIdx.x;
  int b=blk>>4, nb=(blk&15)*64;
  int tid=threadIdx.x, w=tid>>5, l=tid&31;

  for(int e=tid;e<4096;e+=512){
    int j=e>>6, i=e&63;
    wkT[i*68+j]=Wk[e];
    wvT[i*68+j]=Wv[e];
  }
  #pragma unroll
  for(int rr=0;rr<4;rr++){
    int row=w*4+rr;
    const float* xr=inp+(size_t)(b*1024+nb+row)*64;
    float x0=xr[l], x1=xr[l+32];
    float s1=wsum(x0+x1), s2=wsum(x0*x0+x1*x1);
    float m=s1*(1.f/64.f), var=s2*(1.f/64.f)-m*m;
    float rs=rsqrtf(var+1e-5f);
    float v0=(x0-m)*rs*lng[l]+lnb[l];
    float v1=(x1-m)*rs*lng[l+32]+lnb[l+32];
    xsT[l*68+row]=v0; xsT[(l+32)*68+row]=v1;
    float lp=wsum(v0*wiw[l]+v1*wiw[l+32]);
    if(l==0) g_logits[b*1024+nb+row]=lp+wib[0];
  }
  __syncthreads();

  int rp=tid&31, j4=(tid>>5)*4;
  float ka[2][4]={{0.f,0.f,0.f,0.f},{0.f,0.f,0.f,0.f}};
  float va[2][4]={{0.f,0.f,0.f,0.f},{0.f,0.f,0.f,0.f}};
  #pragma unroll 4
  for(int i=0;i<64;i++){
    float2 x2=*(const float2*)&xsT[i*68+rp*2];
    float4 wk4=*(const float4*)&wkT[i*68+j4];
    float4 wv4=*(const float4*)&wvT[i*68+j4];
    ka[0][0]=fmaf(x2.x,wk4.x,ka[0][0]); ka[0][1]=fmaf(x2.x,wk4.y,ka[0][1]);
    ka[0][2]=fmaf(x2.x,wk4.z,ka[0][2]); ka[0][3]=fmaf(x2.x,wk4.w,ka[0][3]);
    ka[1][0]=fmaf(x2.y,wk4.x,ka[1][0]); ka[1][1]=fmaf(x2.y,wk4.y,ka[1][1]);
    ka[1][2]=fmaf(x2.y,wk4.z,ka[1][2]); ka[1][3]=fmaf(x2.y,wk4.w,ka[1][3]);
    va[0][0]=fmaf(x2.x,wv4.x,va[0][0]); va[0][1]=fmaf(x2.x,wv4.y,va[0][1]);
    va[0][2]=fmaf(x2.x,wv4.z,va[0][2]); va[0][3]=fmaf(x2.x,wv4.w,va[0][3]);
    va[1][0]=fmaf(x2.y,wv4.x,va[1][0]); va[1][1]=fmaf(x2.y,wv4.y,va[1][1]);
    va[1][2]=fmaf(x2.y,wv4.z,va[1][2]); va[1][3]=fmaf(x2.y,wv4.w,va[1][3]);
  }
  __syncthreads();
  #pragma unroll
  for(int r=0;r<2;r++)
    #pragma unroll
    for(int jj=0;jj<4;jj++)
      xsT[(j4+jj)*68 + rp*2+r]=ka[r][jj];
  __syncthreads();
  #pragma unroll
  for(int q=0;q<8;q++){
    int o=tid+q*512;
    int d=o>>6, n=o&63;
    g_kT[((size_t)b*64+d)*1024 + nb + n]=xsT[d*68+n];
  }
  __syncthreads();
  #pragma unroll
  for(int r=0;r<2;r++)
    #pragma unroll
    for(int jj=0;jj<4;jj++)
      xsT[(rp*2+r)*68 + j4+jj]=va[r][jj];
  __syncthreads();
  #pragma unroll
  for(int q=0;q<8;q++){
    int o=tid+q*512;
    int n=o>>6, d=o&63;
    g_v[((size_t)(b*1024+nb+n))*64 + d]=xsT[n*68+d];
  }
}

// ================= k_main: 512 threads, 2 n/thread =================
#define SO_UH  0       // 8192
#define SO_VT  8192    // 4096
#define SO_QS  12288   // 512 (transposed qsT[d*8+s])
#define SO_SLT 12800   // 512
#define SO_UPD 13312   // 512
#define SO_EVH 13824   // 80
#define SO_EB  13904   // 8
#define SO_EBI 13912   // 8
#define SO_Q2  13920   // 8
#define SO_PS  13928   // 256 (double buffer 2x128)
#define SO_EVW 14184   // 128
#define SO_DVW 14312   // 128
#define SO_RED 14440   // 16
#define SM_TOT 14456
#define SMEM_BYTES (SM_TOT*4)

#define OUT_POS  131072
#define OUT_ATTN 135168

__global__ void __launch_bounds__(512,2) k_main(float* __restrict__ out,
  const float* __restrict__ noise, const float* __restrict__ mu, const float* __restrict__ sig,
  const float* __restrict__ Wq,
  const float* __restrict__ lsg, const float* __restrict__ lsb,
  const float* __restrict__ wsw, const float* __restrict__ wsb,
  const float* __restrict__ wih, const float* __restrict__ whh,
  const float* __restrict__ bih, const float* __restrict__ bhh,
  const float* __restrict__ f1w, const float* __restrict__ f1b,
  const float* __restrict__ f2w, const float* __restrict__ f2b,
  const float* __restrict__ lfg, const float* __restrict__ lfb){
  extern __shared__ float sm[];
  float* UH  = sm + SO_UH;
  float* VT  = sm + SO_VT;
  float* qs  = sm + SO_QS;
  float* slt = sm + SO_SLT;
  float* upd = sm + SO_UPD;
  float* EVH = sm + SO_EVH;
  float* eb  = sm + SO_EB;
  float* ebi = sm + SO_EBI;
  float* q2  = sm + SO_Q2;
  float* ps  = sm + SO_PS;
  float* evw = sm + SO_EVW;
  float* dvw = sm + SO_DVW;
  float* red = sm + SO_RED;
  int b=blockIdx.x, tid=threadIdx.x, w=tid>>5, l=tid&31;
  int pbuf=0;

  // ---- slots init ----
  { int d=tid&63; slt[tid]=mu[d]+(fabsf(sig[d])+1e-8f)*noise[b*512+tid]; }

  // ---- a = softmax(logits)*8 + eps (registers) ----
  float a2r[2], ia2[2];
  {
    const float* lg=g_logits+b*1024;
    float2 lg2=*(const float2*)&lg[tid*2];
    float mx=fmaxf(lg2.x,lg2.y);
    mx=wmax(mx);
    if(l==0) red[w]=mx;
    __syncthreads();
    float M=-1e30f;
    #pragma unroll
    for(int i=0;i<16;i++) M=fmaxf(M,red[i]);
    float e0=__expf(lg2.x-M), e1=__expf(lg2.y-M);
    float ss=wsum(e0+e1);
    if(l==0) ps[w]=ss;
    __syncthreads();
    float S=0.f;
    #pragma unroll
    for(int i=0;i<16;i++) S+=ps[i];
    float invS=8.f/S;
    a2r[0]=e0*invS+1e-8f; a2r[1]=e1*invS+1e-8f;
    ia2[0]=rcpf(a2r[0]);  ia2[1]=rcpf(a2r[1]);
  }
  __syncthreads();

  for(int itr=0;itr<3;itr++){
    int last=(itr==2);

    // ---- slotproj: LN(slots) -> UH[0..512), ws logits (warps 0..7) ----
    if(w<8){
      float x0=slt[w*64+l], x1=slt[w*64+l+32];
      float s1=wsum(x0+x1), s2=wsum(x0*x0+x1*x1);
      float m=s1*(1.f/64.f), var=s2*(1.f/64.f)-m*m;
      float rs=rsqrtf(var+1e-5f);
      float n0=(x0-m)*rs*lsg[l]+lsb[l];
      float n1=(x1-m)*rs*lsg[l+32]+lsb[l+32];
      UH[w*64+l]=n0; UH[w*64+l+32]=n1;
      float lp=wsum(n0*wsw[l]+n1*wsw[l+32]);
      if(l==0) red[w]=lp+wsb[0];
    }
    __syncthreads();
    if(tid==0){
      float M=red[0];
      for(int i=1;i<8;i++) M=fmaxf(M,red[i]);
      float S=0.f;
      for(int i=0;i<8;i++) S+=__expf(red[i]-M);
      for(int i=0;i<8;i++){
        float bb=8.f*__expf(red[i]-M)/S+1e-8f;
        eb[i]=bb; ebi[i]=rcpf(bb);
      }
    }
    // ---- q projection (1 output/thread) -> qsT[d*8+s], |q|^2 ----
    {
      int s=tid>>6, d=tid&63;
      float q=0.f;
      const float4* wq4=(const float4*)(Wq+d*64);
      const float* sns=UH+s*64;
      #pragma unroll
      for(int i4=0;i4<16;i4++){
        float4 ww=wq4[i4];
        q=fmaf(sns[i4*4+0],ww.x,fmaf(sns[i4*4+1],ww.y,fmaf(sns[i4*4+2],ww.z,fmaf(sns[i4*4+3],ww.w,q))));
      }
      float pq=wsum(q*q);
      if(l==0) ps[w]=pq;
      __syncthreads();           // UH(sn) reads done, ps visible
      qs[d*8+s]=q;               // transposed
      if(tid<8) q2[tid]=ps[2*tid]+ps[2*tid+1];
    }
    __syncthreads();

    // ---- cdist -> E in registers (2 n/thread) ----
    float Ereg[16];
    {
      float q2r[8];
      #pragma unroll
      for(int s=0;s<8;s++) q2r[s]=q2[s];
      float dot[16], k2[2]={0.f,0.f};
      #pragma unroll
      for(int i=0;i<16;i++) dot[i]=0.f;
      const float* kTb = g_kT + (size_t)b*65536;
      for(int d=0;d<64;d++){
        float4 qa=*(const float4*)&qs[d*8];
        float4 qb=*(const float4*)&qs[d*8+4];
        float2 kv=*(const float2*)&kTb[d*1024 + tid*2];
        k2[0]=fmaf(kv.x,kv.x,k2[0]);
        k2[1]=fmaf(kv.y,kv.y,k2[1]);
        dot[0]=fmaf(kv.x,qa.x,dot[0]); dot[1]=fmaf(kv.x,qa.y,dot[1]);
        dot[2]=fmaf(kv.x,qa.z,dot[2]); dot[3]=fmaf(kv.x,qa.w,dot[3]);
        dot[4]=fmaf(kv.x,qb.x,dot[4]); dot[5]=fmaf(kv.x,qb.y,dot[5]);
        dot[6]=fmaf(kv.x,qb.z,dot[6]); dot[7]=fmaf(kv.x,qb.w,dot[7]);
        dot[8]=fmaf(kv.y,qa.x,dot[8]); dot[9]=fmaf(kv.y,qa.y,dot[9]);
        dot[10]=fmaf(kv.y,qa.z,dot[10]); dot[11]=fmaf(kv.y,qa.w,dot[11]);
        dot[12]=fmaf(kv.y,qb.x,dot[12]); dot[13]=fmaf(kv.y,qb.y,dot[13]);
        dot[14]=fmaf(kv.y,qb.z,dot[14]); dot[15]=fmaf(kv.y,qb.w,dot[15]);
      }
      #pragma unroll
      for(int j=0;j<2;j++)
        #pragma unroll
        for(int s=0;s<8;s++)
          Ereg[j*8+s]=__expf(-sqrtf(fmaxf(k2[j]+q2r[s]-2.f*dot[j*8+s],1e-12f)));
    }
    __syncthreads();

    // ---- MESH ----
    float du2[2]={0.f,0.f};
    float euL[2];
    for(int mesh=0;mesh<4;mesh++){
      if(tid<8) EVH[tid]=1.f;
      __syncthreads();
      // forward
      for(int t=0;t<8;t++){
        float ev[8];
        if(t==0){
          #pragma unroll
          for(int s=0;s<8;s++) ev[s]=1.f;
        } else {
          #pragma unroll
          for(int s=0;s<8;s++) ev[s]=evw[w*8+s];
        }
        float colacc[8];
        #pragma unroll
        for(int s=0;s<8;s++) colacc[s]=0.f;
        float eu2[2];
        #pragma unroll
        for(int j=0;j<2;j++){
          float acc=1e-38f;
          #pragma unroll
          for(int s=0;s<8;s++) acc=fmaf(ev[s],Ereg[j*8+s],acc);
          float eu=a2r[j]*rcpf(acc);
          eu2[j]=eu;
          if(t==7) euL[j]=eu;
          #pragma unroll
          for(int s=0;s<8;s++) colacc[s]=fmaf(eu,Ereg[j*8+s],colacc[s]);
        }
        *(float2*)&UH[t*1024+tid*2]=make_float2(eu2[0],eu2[1]);
        float r3=mred8(colacc,l);
        float* pb=ps+(pbuf<<7);
        if(l<8) pb[w*8+br3(l)]=r3;
        __syncthreads();
        if(l<8){
          int vv=br3(l);
          float tot=0.f;
          #pragma unroll
          for(int j=0;j<16;j++) tot+=pb[j*8+vv];
          float evv=eb[vv]*rcpf(tot+1e-38f);
          evw[w*8+vv]=evv;
          if(w==0) EVH[(t+1)*8+vv]=evv;
        }
        __syncwarp();
        pbuf^=1;
      }
      // entropy direct terms
      float Greg[16];
      {
        float ev8[8];
        #pragma unroll
        for(int s=0;s<8;s++) ev8[s]=evw[w*8+s];
        float colacc[8];
        #pragma unroll
        for(int s=0;s<8;s++) colacc[s]=0.f;
        #pragma unroll
        for(int j=0;j<2;j++){
          float ra=0.f;
          #pragma unroll
          for(int s=0;s<8;s++){
            float P=euL[j]*ev8[s]*Ereg[j*8+s];
            float Pe=P+1e-8f;
            float t0=P*(__logf(Pe)+P*rcpf(Pe));
            Greg[j*8+s]=t0; ra+=t0; colacc[s]+=t0;
          }
          du2[j]=-ra;
        }
        float r3=mred8(colacc,l);
        float* pb=ps+(pbuf<<7);
        if(l<8) pb[w*8+br3(l)]=r3;
        __syncthreads();
        if(l<8){
          int vv=br3(l);
          float tot=0.f;
          #pragma unroll
          for(int j=0;j<16;j++) tot+=pb[j*8+vv];
          dvw[w*8+vv]=-tot;
        }
        __syncwarp();
        pbuf^=1;
      }
      // backward t=7..0 (t=0 publishes nothing — dv would be dead)
      for(int t=7;t>=0;t--){
        float wfs[8];
        #pragma unroll
        for(int s=0;s<8;s++)
          wfs[s]=dvw[w*8+s]*EVH[(t+1)*8+s]*ebi[s];
        float2 eut2=*(const float2*)&UH[t*1024+tid*2];
        float fun[2];
        #pragma unroll
        for(int j=0;j<2;j++){
          float eut=(j?eut2.y:eut2.x);
          float t1=0.f;
          #pragma unroll
          for(int s=0;s<8;s++) t1=fmaf(wfs[s],Ereg[j*8+s],t1);
          float uacc=((t==7)?du2[j]:0.f)-eut*t1;
          fun[j]=uacc*eut*ia2[j];
        }
        float colacc[8];
        #pragma unroll
        for(int s=0;s<8;s++){
          float evt=EVH[t*8+s];
          float x0=fun[0]*Ereg[s];
          float x1=fun[1]*Ereg[8+s];
          Greg[s]  =fmaf(Ereg[s]  *wfs[s],eut2.x,fmaf(x0,evt,Greg[s]));
          Greg[8+s]=fmaf(Ereg[8+s]*wfs[s],eut2.y,fmaf(x1,evt,Greg[8+s]));
          colacc[s]=x0+x1;
        }
        if(t>0){
          float r3=mred8(colacc,l);
          float* pb=ps+(pbuf<<7);
          if(l<8) pb[w*8+br3(l)]=r3;
          __syncthreads();
          if(l<8){
            int vv=br3(l);
            float tot=0.f;
            #pragma unroll
            for(int j=0;j<16;j++) tot+=pb[j*8+vv];
            dvw[w*8+vv]=-EVH[t*8+vv]*tot;
          }
          __syncwarp();
          pbuf^=1;
        }
      }
      // E *= exp(3*G)
      #pragma unroll
      for(int i=0;i<16;i++) Ereg[i]*=__expf(3.0f*Greg[i]);
    }

    // ---- final sinkhorn (warm exp(v)) ----
    for(int it=0;it<8;it++){
      float ev[8];
      if(it==0){
        #pragma unroll
        for(int s=0;s<8;s++) ev[s]=EVH[64+s];
      } else {
        #pragma unroll
        for(int s=0;s<8;s++) ev[s]=evw[w*8+s];
      }
      float colacc[8];
      #pragma unroll
      for(int s=0;s<8;s++) colacc[s]=0.f;
      #pragma unroll
      for(int j=0;j<2;j++){
        float acc=1e-38f;
        #pragma unroll
        for(int s=0;s<8;s++) acc=fmaf(ev[s],Ereg[j*8+s],acc);
        float eu=a2r[j]*rcpf(acc);
        if(it==7) euL[j]=eu;
        #pragma unroll
        for(int s=0;s<8;s++) colacc[s]=fmaf(eu,Ereg[j*8+s],colacc[s]);
      }
      float r3=mred8(colacc,l);
      float* pb=ps+(pbuf<<7);
      if(l<8) pb[w*8+br3(l)]=r3;
      __syncthreads();
      if(l<8){
        int vv=br3(l);
        float tot=0.f;
        #pragma unroll
        for(int j=0;j<16;j++) tot+=pb[j*8+vv];
        evw[w*8+vv]=eb[vv]*rcpf(tot+1e-38f);
      }
      __syncwarp();
      pbuf^=1;
    }

    // ---- P = EU*EV*E -> UH (and attn out) ----
    {
      float evf[8];
      #pragma unroll
      for(int s=0;s<8;s++) evf[s]=evw[w*8+s];
      #pragma unroll
      for(int s=0;s<8;s++){
        float2 P2=make_float2(euL[0]*evf[s]*Ereg[s], euL[1]*evf[s]*Ereg[8+s]);
        *(float2*)&UH[s*1024+tid*2]=P2;
        if(last) *(float2*)&out[OUT_ATTN+b*8192+s*1024+tid*2]=P2;
      }
    }
    __syncthreads();

    // ---- slot_pos (last): warp w -> slot w (warps 0..7) ----
    if(last && w<8){
      const float* Pp=UH+w*1024;
      float gx=0.f,gy=0.f;
      #pragma unroll 4
      for(int i=l;i<1024;i+=32){
        float p=Pp[i];
        gx=fmaf(p,(float)(i&31),gx);
        gy=fmaf(p,(float)(i>>5),gy);
      }
      gx=wsum(gx); gy=wsum(gy);
      if(l==0){
        out[OUT_POS+(b*8+w)*2+0]=gx*(1.f/31.f);
        out[OUT_POS+(b*8+w)*2+1]=gy*(1.f/31.f);
      }
    }

    // ---- updates = P @ v via VT tiles (thread -> one (s,d)) ----
    {
      int d=tid&63, s=tid>>6;
      float acc=0.f;
      const float4* gv4=(const float4*)(g_v+(size_t)b*65536);
      float4* VT4=(float4*)VT;
      for(int t16=0;t16<16;t16++){
        VT4[tid]=gv4[t16*1024+tid];
        VT4[tid+512]=gv4[t16*1024+tid+512];
        __syncthreads();
        const float* PA=UH+s*1024+t16*64;
        #pragma unroll 8
        for(int r=0;r<64;r++)
          acc=fmaf(PA[r],VT[r*64+d],acc);
        __syncthreads();
      }
      upd[tid]=acc;
    }
    __syncthreads();

    // ---- GRU (scratch in UH) ----
    #pragma unroll
    for(int k=0;k<3;k++){
      int idx=tid+k*512;
      int s2=idx/192, j=idx-s2*192;
      float a=bih[j], c=bhh[j];
      const float4* w1=(const float4*)(wih+j*64);
      const float4* w2=(const float4*)(whh+j*64);
      const float* us=upd+s2*64;
      const float* hs=slt+s2*64;
      #pragma unroll
      for(int i4=0;i4<16;i4++){
        float4 A=w1[i4], Bm=w2[i4];
        a=fmaf(us[i4*4+0],A.x,fmaf(us[i4*4+1],A.y,fmaf(us[i4*4+2],A.z,fmaf(us[i4*4+3],A.w,a))));
        c=fmaf(hs[i4*4+0],Bm.x,fmaf(hs[i4*4+1],Bm.y,fmaf(hs[i4*4+2],Bm.z,fmaf(hs[i4*4+3],Bm.w,c))));
      }
      UH[idx]=a; UH[1536+idx]=c;
    }
    __syncthreads();
    {
      int s2=tid>>6, d=tid&63;
      float r=sigf(UH[s2*192+d]+UH[1536+s2*192+d]);
      float z=sigf(UH[s2*192+64+d]+UH[1536+s2*192+64+d]);
      float nn=tanhf(UH[s2*192+128+d]+r*UH[1536+s2*192+128+d]);
      UH[3072+tid]=(1.f-z)*nn+z*slt[tid];
    }
    __syncthreads();
    // LN(ff)
    if(w<8){
      float x0=UH[3072+w*64+l], x1=UH[3072+w*64+l+32];
      float s1=wsum(x0+x1), s2=wsum(x0*x0+x1*x1);
      float m=s1*(1.f/64.f), var=s2*(1.f/64.f)-m*m;
      float rs=rsqrtf(var+1e-5f);
      UH[3584+w*64+l]   =(x0-m)*rs*lfg[l]   +lfb[l];
      UH[3584+w*64+l+32]=(x1-m)*rs*lfg[l+32]+lfb[l+32];
    }
    __syncthreads();
    // fc1
    #pragma unroll
    for(int k=0;k<2;k++){
      int idx=tid+k*512;
      int s2=idx>>7, j=idx&127;
      float a=f1b[j];
      const float4* w1=(const float4*)(f1w+j*64);
      const float* xsr=UH+3584+s2*64;
      #pragma unroll
      for(int i4=0;i4<16;i4++){
        float4 A=w1[i4];
        a=fmaf(xsr[i4*4+0],A.x,fmaf(xsr[i4*4+1],A.y,fmaf(xsr[i4*4+2],A.z,fmaf(xsr[i4*4+3],A.w,a))));
      }
      UH[4096+idx]=fmaxf(a,0.f);
    }
    __syncthreads();
    // fc2 + residual
    {
      int s2=tid>>6, d=tid&63;
      float a=f2b[d];
      const float4* w2=(const float4*)(f2w+d*128);
      const float* hs=UH+4096+s2*128;
      #pragma unroll
      for(int i4=0;i4<32;i4++){
        float4 A=w2[i4];
        a=fmaf(hs[i4*4+0],A.x,fmaf(hs[i4*4+1],A.y,fmaf(hs[i4*4+2],A.z,fmaf(hs[i4*4+3],A.w,a))));
      }
      float val=UH[3072+tid]+a;
      slt[tid]=val;
      if(last) out[b*512+tid]=val;
    }
    __syncthreads();
  }
}

extern "C" void kernel_launch(void* const* d_in, const int* in_sizes, int n_in,
                              void* d_out, int out_size){
  const float* inp  =(const float*)d_in[0];
  const float* noise=(const float*)d_in[1];
  const float* mu   =(const float*)d_in[2];
  const float* sig  =(const float*)d_in[3];
  const float* Wq   =(const float*)d_in[4];
  const float* Wk   =(const float*)d_in[5];
  const float* Wv   =(const float*)d_in[6];
  const float* wih  =(const float*)d_in[7];
  const float* whh  =(const float*)d_in[8];
  const float* bih  =(const float*)d_in[9];
  const float* bhh  =(const float*)d_in[10];
  const float* f1w  =(const float*)d_in[11];
  const float* f1b  =(const float*)d_in[12];
  const float* f2w  =(const float*)d_in[13];
  const float* f2b  =(const float*)d_in[14];
  const float* lig  =(const float*)d_in[15];
  const float* lib  =(const float*)d_in[16];
  const float* lsg  =(const float*)d_in[17];
  const float* lsb  =(const float*)d_in[18];
  const float* lfg  =(const float*)d_in[19];
  const float* lfb  =(const float*)d_in[20];
  const float* wiw  =(const float*)d_in[21];
  const float* wib  =(const float*)d_in[22];
  const float* wsw  =(const float*)d_in[23];
  const float* wsb  =(const float*)d_in[24];
  float* out=(float*)d_out;

  cudaFuncSetAttribute(k_main, cudaFuncAttributeMaxDynamicSharedMemorySize, SMEM_BYTES);

  k_prep<<<BB*16,512>>>(inp,lig,lib,Wk,Wv,wiw,wib);
  k_main<<<BB,512,SMEM_BYTES>>>(out,noise,mu,sig,Wq,lsg,lsb,wsw,wsb,
                                wih,whh,bih,bhh,f1w,f1b,f2w,f2b,lfg,lfb);
  (void)in_sizes; (void)n_in; (void)out_size;
}

// round 14
// speedup vs baseline: 1.2134x; 1.2134x over previous
#include <cuda_runtime.h>
#include <cuda_bf16.h>
#include <math.h>

#define BB 256
#define NN 1024
#define NSL 8

// ---------------- device-global scratch ----------------
__device__ float g_kT[BB*64*NN];   // [b][d][n]
__device__ float g_v[BB*NN*64];    // [b][n][d]
__device__ float g_logits[BB*NN];

__device__ __forceinline__ float wsum(float v){
  #pragma unroll
  for(int o=16;o;o>>=1) v += __shfl_xor_sync(0xffffffffu, v, o);
  return v;
}
__device__ __forceinline__ float wmax(float v){
  #pragma unroll
  for(int o=16;o;o>>=1) v = fmaxf(v, __shfl_xor_sync(0xffffffffu, v, o));
  return v;
}
__device__ __forceinline__ float sigf(float x){ return 1.f/(1.f+__expf(-x)); }
__device__ __forceinline__ float rcpf(float x){
  float r; asm("rcp.approx.ftz.f32 %0,%1;":"=f"(r):"f"(x)); return r;
}
__device__ __forceinline__ int br3(int p){ return ((p&1)<<2)|(p&2)|((p&4)>>2); }

// multi-value butterfly: warp-reduce 8 values in 9 shuffles; returns sum of value br3(l&7).
__device__ __forceinline__ float mred8(const float* c, int l){
  float r1[4], r2[2], r3;
  #pragma unroll
  for(int i=0;i<4;i++){
    float send=(l&1)? c[i] : c[i+4];
    float t=__shfl_xor_sync(0xffffffffu, send, 1);
    r1[i]=((l&1)? c[i+4] : c[i])+t;
  }
  #pragma unroll
  for(int i=0;i<2;i++){
    float send=(l&2)? r1[i] : r1[i+2];
    float t=__shfl_xor_sync(0xffffffffu, send, 2);
    r2[i]=((l&2)? r1[i+2] : r1[i])+t;
  }
  {
    float send=(l&4)? r2[0] : r2[1];
    float t=__shfl_xor_sync(0xffffffffu, send, 4);
    r3=((l&4)? r2[1] : r2[0])+t;
  }
  r3+=__shfl_xor_sync(0xffffffffu, r3, 8);
  r3+=__shfl_xor_sync(0xffffffffu, r3, 16);
  return r3;
}

// ================= k_prep: LN(inputs), k/v proj, wi logits; 4 row-blocks per CTA =================
// grid = 256*4 = 1024, 512 threads
__global__ void __launch_bounds__(512,3) k_prep(const float* __restrict__ inp,
        const float* __restrict__ lng, const float* __restrict__ lnb,
        const float* __restrict__ Wk, const float* __restrict__ Wv,
        const float* __restrict__ wiw, const float* __restrict__ wib){
  __shared__ float wkT[64*68];
  __shared__ float wvT[64*68];
  __shared__ float xsT[64*68];
  int blk=blockIdx.x;
  int b=blk>>2;
  int tid=threadIdx.x, w=tid>>5, l=tid&31;

  // stage transposed weights once
  for(int e=tid;e<4096;e+=512){
    int j=e>>6, i=e&63;
    wkT[i*68+j]=Wk[e];
    wvT[i*68+j]=Wv[e];
  }
  __syncthreads();

  for(int bl=0;bl<4;bl++){
    int nb=((blk&3)*4+bl)*64;
    // LN + logits
    #pragma unroll
    for(int rr=0;rr<4;rr++){
      int row=w*4+rr;
      const float* xr=inp+(size_t)(b*1024+nb+row)*64;
      float x0=xr[l], x1=xr[l+32];
      float s1=wsum(x0+x1), s2=wsum(x0*x0+x1*x1);
      float m=s1*(1.f/64.f), var=s2*(1.f/64.f)-m*m;
      float rs=rsqrtf(var+1e-5f);
      float v0=(x0-m)*rs*lng[l]+lnb[l];
      float v1=(x1-m)*rs*lng[l+32]+lnb[l+32];
      xsT[l*68+row]=v0; xsT[(l+32)*68+row]=v1;
      float lp=wsum(v0*wiw[l]+v1*wiw[l+32]);
      if(l==0) g_logits[b*1024+nb+row]=lp+wib[0];
    }
    __syncthreads();

    int rp=tid&31, j4=(tid>>5)*4;
    float ka[2][4]={{0.f,0.f,0.f,0.f},{0.f,0.f,0.f,0.f}};
    float va[2][4]={{0.f,0.f,0.f,0.f},{0.f,0.f,0.f,0.f}};
    #pragma unroll 4
    for(int i=0;i<64;i++){
      float2 x2=*(const float2*)&xsT[i*68+rp*2];
      float4 wk4=*(const float4*)&wkT[i*68+j4];
      float4 wv4=*(const float4*)&wvT[i*68+j4];
      ka[0][0]=fmaf(x2.x,wk4.x,ka[0][0]); ka[0][1]=fmaf(x2.x,wk4.y,ka[0][1]);
      ka[0][2]=fmaf(x2.x,wk4.z,ka[0][2]); ka[0][3]=fmaf(x2.x,wk4.w,ka[0][3]);
      ka[1][0]=fmaf(x2.y,wk4.x,ka[1][0]); ka[1][1]=fmaf(x2.y,wk4.y,ka[1][1]);
      ka[1][2]=fmaf(x2.y,wk4.z,ka[1][2]); ka[1][3]=fmaf(x2.y,wk4.w,ka[1][3]);
      va[0][0]=fmaf(x2.x,wv4.x,va[0][0]); va[0][1]=fmaf(x2.x,wv4.y,va[0][1]);
      va[0][2]=fmaf(x2.x,wv4.z,va[0][2]); va[0][3]=fmaf(x2.x,wv4.w,va[0][3]);
      va[1][0]=fmaf(x2.y,wv4.x,va[1][0]); va[1][1]=fmaf(x2.y,wv4.y,va[1][1]);
      va[1][2]=fmaf(x2.y,wv4.z,va[1][2]); va[1][3]=fmaf(x2.y,wv4.w,va[1][3]);
    }
    __syncthreads();
    #pragma unroll
    for(int r=0;r<2;r++)
      #pragma unroll
      for(int jj=0;jj<4;jj++)
        xsT[(j4+jj)*68 + rp*2+r]=ka[r][jj];
    __syncthreads();
    #pragma unroll
    for(int q=0;q<8;q++){
      int o=tid+q*512;
      int d=o>>6, n=o&63;
      g_kT[((size_t)b*64+d)*1024 + nb + n]=xsT[d*68+n];
    }
    __syncthreads();
    #pragma unroll
    for(int r=0;r<2;r++)
      #pragma unroll
      for(int jj=0;jj<4;jj++)
        xsT[(rp*2+r)*68 + j4+jj]=va[r][jj];
    __syncthreads();
    #pragma unroll
    for(int q=0;q<8;q++){
      int o=tid+q*512;
      int n=o>>6, d=o&63;
      g_v[((size_t)(b*1024+nb+n))*64 + d]=xsT[n*68+d];
    }
    __syncthreads();
  }
}

// ================= k_main: 256 threads, 4 n/thread (pairs 2t,2t+1,512+2t,512+2t+1) =================
#define SO_UH  0       // 8192
#define SO_VT  8192    // 4096
#define SO_QS  12288   // 512 (qsT[d*8+s])
#define SO_SLT 12800   // 512
#define SO_UPD 13312   // 512
#define SO_EVH 13824   // 80
#define SO_EB  13904   // 8
#define SO_EBI 13912   // 8
#define SO_Q2  13920   // 8
#define SO_PS  13936   // 128 (double buffer 2x64, [vv*8+w])
#define SO_EVW 14064   // 64
#define SO_DVW 14128   // 64
#define SO_RED 14192   // 16
#define SM_TOT 14208
#define SMEM_BYTES (SM_TOT*4)

#define OUT_POS  131072
#define OUT_ATTN 135168

__global__ void __launch_bounds__(256,2) k_main(float* __restrict__ out,
  const float* __restrict__ noise, const float* __restrict__ mu, const float* __restrict__ sig,
  const float* __restrict__ Wq,
  const float* __restrict__ lsg, const float* __restrict__ lsb,
  const float* __restrict__ wsw, const float* __restrict__ wsb,
  const float* __restrict__ wih, const float* __restrict__ whh,
  const float* __restrict__ bih, const float* __restrict__ bhh,
  const float* __restrict__ f1w, const float* __restrict__ f1b,
  const float* __restrict__ f2w, const float* __restrict__ f2b,
  const float* __restrict__ lfg, const float* __restrict__ lfb){
  extern __shared__ float sm[];
  float* UH  = sm + SO_UH;
  float* VT  = sm + SO_VT;
  float* qs  = sm + SO_QS;
  float* slt = sm + SO_SLT;
  float* upd = sm + SO_UPD;
  float* EVH = sm + SO_EVH;
  float* eb  = sm + SO_EB;
  float* ebi = sm + SO_EBI;
  float* q2  = sm + SO_Q2;
  float* ps  = sm + SO_PS;
  float* evw = sm + SO_EVW;
  float* dvw = sm + SO_DVW;
  float* red = sm + SO_RED;
  int b=blockIdx.x, tid=threadIdx.x, w=tid>>5, l=tid&31;
  int pbuf=0;
  int n0=2*tid;   // thread n-set: n0, n0+1, n0+512, n0+513

  // ---- slots init ----
  #pragma unroll
  for(int k=0;k<2;k++){
    int idx=tid+k*256; int d=idx&63;
    slt[idx]=mu[d]+(fabsf(sig[d])+1e-8f)*noise[b*512+idx];
  }

  // ---- a = softmax(logits)*8 + eps (registers) ----
  float a4[4], ia4[4];
  {
    const float* lg=g_logits+b*1024;
    float2 A=*(const float2*)&lg[n0];
    float2 Bv=*(const float2*)&lg[n0+512];
    float mx=fmaxf(fmaxf(A.x,A.y),fmaxf(Bv.x,Bv.y));
    mx=wmax(mx);
    if(l==0) red[w]=mx;
    __syncthreads();
    float M=-1e30f;
    #pragma unroll
    for(int i=0;i<8;i++) M=fmaxf(M,red[i]);
    float e00=__expf(A.x-M), e01=__expf(A.y-M);
    float e10=__expf(Bv.x-M), e11=__expf(Bv.y-M);
    float ss=wsum(e00+e01+e10+e11);
    if(l==0) ps[w]=ss;
    __syncthreads();
    float S=0.f;
    #pragma unroll
    for(int i=0;i<8;i++) S+=ps[i];
    float invS=8.f/S;
    a4[0]=e00*invS+1e-8f; a4[1]=e01*invS+1e-8f;
    a4[2]=e10*invS+1e-8f; a4[3]=e11*invS+1e-8f;
    #pragma unroll
    for(int i=0;i<4;i++) ia4[i]=rcpf(a4[i]);
  }
  __syncthreads();

  for(int itr=0;itr<3;itr++){
    int last=(itr==2);

    // ---- slotproj: LN(slots) -> UH[0..512), ws logits ----
    {
      float x0=slt[w*64+l], x1=slt[w*64+l+32];
      float s1=wsum(x0+x1), s2=wsum(x0*x0+x1*x1);
      float m=s1*(1.f/64.f), var=s2*(1.f/64.f)-m*m;
      float rs=rsqrtf(var+1e-5f);
      float nn0=(x0-m)*rs*lsg[l]+lsb[l];
      float nn1=(x1-m)*rs*lsg[l+32]+lsb[l+32];
      UH[w*64+l]=nn0; UH[w*64+l+32]=nn1;
      float lp=wsum(nn0*wsw[l]+nn1*wsw[l+32]);
      if(l==0) red[w]=lp+wsb[0];
    }
    __syncthreads();
    if(tid==0){
      float M=red[0];
      for(int i=1;i<8;i++) M=fmaxf(M,red[i]);
      float S=0.f;
      for(int i=0;i<8;i++) S+=__expf(red[i]-M);
      for(int i=0;i<8;i++){
        float bb=8.f*__expf(red[i]-M)/S+1e-8f;
        eb[i]=bb; ebi[i]=rcpf(bb);
      }
    }
    // ---- q projection (2 outputs/thread) -> qsT[d*8+s], |q|^2 ----
    {
      float qv[2]; int sidx[2], didx[2];
      #pragma unroll
      for(int k=0;k<2;k++){
        int idx=tid+k*256;
        int s=idx>>6, d=idx&63;
        sidx[k]=s; didx[k]=d;
        float q=0.f;
        const float4* wq4=(const float4*)(Wq+d*64);
        const float* sns=UH+s*64;
        #pragma unroll
        for(int i4=0;i4<16;i4++){
          float4 ww=wq4[i4];
          q=fmaf(sns[i4*4+0],ww.x,fmaf(sns[i4*4+1],ww.y,fmaf(sns[i4*4+2],ww.z,fmaf(sns[i4*4+3],ww.w,q))));
        }
        qv[k]=q;
        float pq=wsum(q*q);
        if(l==0) ps[k*8+w]=pq;
      }
      __syncthreads();
      qs[didx[0]*8+sidx[0]]=qv[0];
      qs[didx[1]*8+sidx[1]]=qv[1];
      if(tid<8){
        int base=(tid>>2)*8+(tid&3)*2;
        q2[tid]=ps[base]+ps[base+1];
      }
    }
    __syncthreads();

    // ---- cdist -> E in registers ----
    float Ereg[16+16];  // [g*8+s], g = h*2+j
    {
      float q2r[8];
      #pragma unroll
      for(int s=0;s<8;s++) q2r[s]=q2[s];
      float dot[32], k2[4]={0.f,0.f,0.f,0.f};
      #pragma unroll
      for(int i=0;i<32;i++) dot[i]=0.f;
      const float* kTb = g_kT + (size_t)b*65536;
      for(int d=0;d<64;d++){
        float4 qa=*(const float4*)&qs[d*8];
        float4 qb=*(const float4*)&qs[d*8+4];
        float2 kA=*(const float2*)&kTb[d*1024 + n0];
        float2 kB=*(const float2*)&kTb[d*1024 + n0 + 512];
        float kv[4]={kA.x,kA.y,kB.x,kB.y};
        #pragma unroll
        for(int g=0;g<4;g++){
          float kk=kv[g];
          k2[g]=fmaf(kk,kk,k2[g]);
          dot[g*8+0]=fmaf(kk,qa.x,dot[g*8+0]); dot[g*8+1]=fmaf(kk,qa.y,dot[g*8+1]);
          dot[g*8+2]=fmaf(kk,qa.z,dot[g*8+2]); dot[g*8+3]=fmaf(kk,qa.w,dot[g*8+3]);
          dot[g*8+4]=fmaf(kk,qb.x,dot[g*8+4]); dot[g*8+5]=fmaf(kk,qb.y,dot[g*8+5]);
          dot[g*8+6]=fmaf(kk,qb.z,dot[g*8+6]); dot[g*8+7]=fmaf(kk,qb.w,dot[g*8+7]);
        }
      }
      #pragma unroll
      for(int g=0;g<4;g++)
        #pragma unroll
        for(int s=0;s<8;s++)
          Ereg[g*8+s]=__expf(-sqrtf(fmaxf(k2[g]+q2r[s]-2.f*dot[g*8+s],1e-12f)));
    }
    __syncthreads();

    // ---- MESH ----
    float du4[4]={0.f,0.f,0.f,0.f};
    float euL[4];
    for(int mesh=0;mesh<4;mesh++){
      if(tid<8) EVH[tid]=1.f;
      __syncthreads();
      // forward
      for(int t=0;t<8;t++){
        float ev[8];
        if(t==0){
          #pragma unroll
          for(int s=0;s<8;s++) ev[s]=1.f;
        } else {
          float4 e0=*(const float4*)&evw[w*8];
          float4 e1=*(const float4*)&evw[w*8+4];
          ev[0]=e0.x; ev[1]=e0.y; ev[2]=e0.z; ev[3]=e0.w;
          ev[4]=e1.x; ev[5]=e1.y; ev[6]=e1.z; ev[7]=e1.w;
        }
        float colacc[8];
        #pragma unroll
        for(int s=0;s<8;s++) colacc[s]=0.f;
        float eu4[4];
        #pragma unroll
        for(int g=0;g<4;g++){
          float acc=1e-38f;
          #pragma unroll
          for(int s=0;s<8;s++) acc=fmaf(ev[s],Ereg[g*8+s],acc);
          float eu=a4[g]*rcpf(acc);
          eu4[g]=eu;
          if(t==7) euL[g]=eu;
          #pragma unroll
          for(int s=0;s<8;s++) colacc[s]=fmaf(eu,Ereg[g*8+s],colacc[s]);
        }
        *(float2*)&UH[t*1024+n0]    =make_float2(eu4[0],eu4[1]);
        *(float2*)&UH[t*1024+n0+512]=make_float2(eu4[2],eu4[3]);
        float r3=mred8(colacc,l);
        float* pb=ps+(pbuf<<6);
        if(l<8) pb[br3(l)*8+w]=r3;
        __syncthreads();
        if(l<8){
          int vv=br3(l);
          float4 A=*(const float4*)&pb[vv*8];
          float4 Bv=*(const float4*)&pb[vv*8+4];
          float tot=A.x+A.y+A.z+A.w+Bv.x+Bv.y+Bv.z+Bv.w;
          float evv=eb[vv]*rcpf(tot+1e-38f);
          evw[w*8+vv]=evv;
          if(w==0) EVH[(t+1)*8+vv]=evv;
        }
        __syncwarp();
        pbuf^=1;
      }
      // entropy direct terms
      float Greg[32];
      {
        float4 e0=*(const float4*)&evw[w*8];
        float4 e1=*(const float4*)&evw[w*8+4];
        float ev8[8]={e0.x,e0.y,e0.z,e0.w,e1.x,e1.y,e1.z,e1.w};
        float colacc[8];
        #pragma unroll
        for(int s=0;s<8;s++) colacc[s]=0.f;
        #pragma unroll
        for(int g=0;g<4;g++){
          float ra=0.f;
          #pragma unroll
          for(int s=0;s<8;s++){
            float P=euL[g]*ev8[s]*Ereg[g*8+s];
            float Pe=P+1e-8f;
            float t0=P*(__logf(Pe)+P*rcpf(Pe));
            Greg[g*8+s]=t0; ra+=t0; colacc[s]+=t0;
          }
          du4[g]=-ra;
        }
        float r3=mred8(colacc,l);
        float* pb=ps+(pbuf<<6);
        if(l<8) pb[br3(l)*8+w]=r3;
        __syncthreads();
        if(l<8){
          int vv=br3(l);
          float4 A=*(const float4*)&pb[vv*8];
          float4 Bv=*(const float4*)&pb[vv*8+4];
          dvw[w*8+vv]=-(A.x+A.y+A.z+A.w+Bv.x+Bv.y+Bv.z+Bv.w);
        }
        __syncwarp();
        pbuf^=1;
      }
      // backward t=7..0 (t=0 publishes nothing)
      for(int t=7;t>=0;t--){
        float4 d0=*(const float4*)&dvw[w*8];
        float4 d1=*(const float4*)&dvw[w*8+4];
        float4 h0=*(const float4*)&EVH[(t+1)*8];
        float4 h1=*(const float4*)&EVH[(t+1)*8+4];
        float4 b0=*(const float4*)&ebi[0];
        float4 b1=*(const float4*)&ebi[4];
        float wfs[8]={d0.x*h0.x*b0.x, d0.y*h0.y*b0.y, d0.z*h0.z*b0.z, d0.w*h0.w*b0.w,
                      d1.x*h1.x*b1.x, d1.y*h1.y*b1.y, d1.z*h1.z*b1.z, d1.w*h1.w*b1.w};
        float4 m0=*(const float4*)&EVH[t*8];
        float4 m1=*(const float4*)&EVH[t*8+4];
        float ems[8]={m0.x,m0.y,m0.z,m0.w,m1.x,m1.y,m1.z,m1.w};
        float2 uA=*(const float2*)&UH[t*1024+n0];
        float2 uB=*(const float2*)&UH[t*1024+n0+512];
        float ut[4]={uA.x,uA.y,uB.x,uB.y};
        float fun[4];
        #pragma unroll
        for(int g=0;g<4;g++){
          float t1=0.f;
          #pragma unroll
          for(int s=0;s<8;s++) t1=fmaf(wfs[s],Ereg[g*8+s],t1);
          float uacc=((t==7)?du4[g]:0.f)-ut[g]*t1;
          fun[g]=uacc*ut[g]*ia4[g];
        }
        float colacc[8];
        #pragma unroll
        for(int s=0;s<8;s++){
          float x0=fun[0]*Ereg[s];
          float x1=fun[1]*Ereg[8+s];
          float x2=fun[2]*Ereg[16+s];
          float x3=fun[3]*Ereg[24+s];
          colacc[s]=x0+x1+x2+x3;
          float evt=ems[s];
          Greg[s]   =fmaf(Ereg[s]   *wfs[s],ut[0],fmaf(x0,evt,Greg[s]));
          Greg[8+s] =fmaf(Ereg[8+s] *wfs[s],ut[1],fmaf(x1,evt,Greg[8+s]));
          Greg[16+s]=fmaf(Ereg[16+s]*wfs[s],ut[2],fmaf(x2,evt,Greg[16+s]));
          Greg[24+s]=fmaf(Ereg[24+s]*wfs[s],ut[3],fmaf(x3,evt,Greg[24+s]));
        }
        if(t>0){
          float r3=mred8(colacc,l);
          float* pb=ps+(pbuf<<6);
          if(l<8) pb[br3(l)*8+w]=r3;
          __syncthreads();
          if(l<8){
            int vv=br3(l);
            float4 A=*(const float4*)&pb[vv*8];
            float4 Bv=*(const float4*)&pb[vv*8+4];
            dvw[w*8+vv]=-EVH[t*8+vv]*(A.x+A.y+A.z+A.w+Bv.x+Bv.y+Bv.z+Bv.w);
          }
          __syncwarp();
          pbuf^=1;
        }
      }
      // E *= exp(3*G)
      #pragma unroll
      for(int i=0;i<32;i++) Ereg[i]*=__expf(3.0f*Greg[i]);
    }

    // ---- final sinkhorn (warm exp(v)) ----
    for(int it=0;it<8;it++){
      float ev[8];
      if(it==0){
        float4 e0=*(const float4*)&EVH[64];
        float4 e1=*(const float4*)&EVH[68];
        ev[0]=e0.x; ev[1]=e0.y; ev[2]=e0.z; ev[3]=e0.w;
        ev[4]=e1.x; ev[5]=e1.y; ev[6]=e1.z; ev[7]=e1.w;
      } else {
        float4 e0=*(const float4*)&evw[w*8];
        float4 e1=*(const float4*)&evw[w*8+4];
        ev[0]=e0.x; ev[1]=e0.y; ev[2]=e0.z; ev[3]=e0.w;
        ev[4]=e1.x; ev[5]=e1.y; ev[6]=e1.z; ev[7]=e1.w;
      }
      float colacc[8];
      #pragma unroll
      for(int s=0;s<8;s++) colacc[s]=0.f;
      #pragma unroll
      for(int g=0;g<4;g++){
        float acc=1e-38f;
        #pragma unroll
        for(int s=0;s<8;s++) acc=fmaf(ev[s],Ereg[g*8+s],acc);
        float eu=a4[g]*rcpf(acc);
        if(it==7) euL[g]=eu;
        #pragma unroll
        for(int s=0;s<8;s++) colacc[s]=fmaf(eu,Ereg[g*8+s],colacc[s]);
      }
      float r3=mred8(colacc,l);
      float* pb=ps+(pbuf<<6);
      if(l<8) pb[br3(l)*8+w]=r3;
      __syncthreads();
      if(l<8){
        int vv=br3(l);
        float4 A=*(const float4*)&pb[vv*8];
        float4 Bv=*(const float4*)&pb[vv*8+4];
        evw[w*8+vv]=eb[vv]*rcpf(A.x+A.y+A.z+A.w+Bv.x+Bv.y+Bv.z+Bv.w+1e-38f);
      }
      __syncwarp();
      pbuf^=1;
    }

    // ---- P = EU*EV*E -> UH (and attn out) ----
    {
      float4 e0=*(const float4*)&evw[w*8];
      float4 e1=*(const float4*)&evw[w*8+4];
      float evf[8]={e0.x,e0.y,e0.z,e0.w,e1.x,e1.y,e1.z,e1.w};
      #pragma unroll
      for(int s=0;s<8;s++){
        float2 PA=make_float2(euL[0]*evf[s]*Ereg[s],    euL[1]*evf[s]*Ereg[8+s]);
        float2 PB=make_float2(euL[2]*evf[s]*Ereg[16+s], euL[3]*evf[s]*Ereg[24+s]);
        *(float2*)&UH[s*1024+n0]    =PA;
        *(float2*)&UH[s*1024+n0+512]=PB;
        if(last){
          *(float2*)&out[OUT_ATTN+b*8192+s*1024+n0]    =PA;
          *(float2*)&out[OUT_ATTN+b*8192+s*1024+n0+512]=PB;
        }
      }
    }
    __syncthreads();

    // ---- slot_pos (last): warp w -> slot w ----
    if(last){
      const float* Pp=UH+w*1024;
      float gx=0.f,gy=0.f;
      #pragma unroll 4
      for(int i=l;i<1024;i+=32){
        float p=Pp[i];
        gx=fmaf(p,(float)(i&31),gx);
        gy=fmaf(p,(float)(i>>5),gy);
      }
      gx=wsum(gx); gy=wsum(gy);
      if(l==0){
        out[OUT_POS+(b*8+w)*2+0]=gx*(1.f/31.f);
        out[OUT_POS+(b*8+w)*2+1]=gy*(1.f/31.f);
      }
    }

    // ---- updates = P @ v via VT tiles (thread -> (s, d-pair)) ----
    {
      int s=tid>>5, dd=(tid&31)*2;
      float accx=0.f, accy=0.f;
      const float4* gv4=(const float4*)(g_v+(size_t)b*65536);
      float4* VT4=(float4*)VT;
      for(int t16=0;t16<16;t16++){
        #pragma unroll
        for(int j=0;j<4;j++) VT4[tid+j*256]=gv4[t16*1024+tid+j*256];
        __syncthreads();
        const float* PA=UH+s*1024+t16*64;
        #pragma unroll 8
        for(int r=0;r<64;r++){
          float p=PA[r];
          float2 v2=*(const float2*)&VT[r*64+dd];
          accx=fmaf(p,v2.x,accx);
          accy=fmaf(p,v2.y,accy);
        }
        __syncthreads();
      }
      *(float2*)&upd[s*64+dd]=make_float2(accx,accy);
    }
    __syncthreads();

    // ---- GRU (scratch in UH) ----
    #pragma unroll
    for(int k=0;k<6;k++){
      int idx=tid+k*256;
      int s2=idx/192, j=idx-s2*192;
      float a=bih[j], c=bhh[j];
      const float4* w1=(const float4*)(wih+j*64);
      const float4* w2=(const float4*)(whh+j*64);
      const float4* us4=(const float4*)(upd+s2*64);
      const float4* hs4=(const float4*)(slt+s2*64);
      #pragma unroll
      for(int i4=0;i4<16;i4++){
        float4 A=w1[i4], Bm=w2[i4];
        float4 U4=us4[i4], H4=hs4[i4];
        a=fmaf(U4.x,A.x,fmaf(U4.y,A.y,fmaf(U4.z,A.z,fmaf(U4.w,A.w,a))));
        c=fmaf(H4.x,Bm.x,fmaf(H4.y,Bm.y,fmaf(H4.z,Bm.z,fmaf(H4.w,Bm.w,c))));
      }
      UH[idx]=a; UH[1536+idx]=c;
    }
    __syncthreads();
    #pragma unroll
    for(int k=0;k<2;k++){
      int idx=tid+k*256;
      int s2=idx>>6, d=idx&63;
      float r=sigf(UH[s2*192+d]+UH[1536+s2*192+d]);
      float z=sigf(UH[s2*192+64+d]+UH[1536+s2*192+64+d]);
      float nn=tanhf(UH[s2*192+128+d]+r*UH[1536+s2*192+128+d]);
      UH[3072+idx]=(1.f-z)*nn+z*slt[idx];
    }
    __syncthreads();
    // LN(ff)
    {
      float x0=UH[3072+w*64+l], x1=UH[3072+w*64+l+32];
      float s1=wsum(x0+x1), s2=wsum(x0*x0+x1*x1);
      float m=s1*(1.f/64.f), var=s2*(1.f/64.f)-m*m;
      float rs=rsqrtf(var+1e-5f);
      UH[3584+w*64+l]   =(x0-m)*rs*lfg[l]   +lfb[l];
      UH[3584+w*64+l+32]=(x1-m)*rs*lfg[l+32]+lfb[l+32];
    }
    __syncthreads();
    // fc1
    #pragma unroll
    for(int k=0;k<4;k++){
      int idx=tid+k*256;
      int s2=idx>>7, j=idx&127;
      float a=f1b[j];
      const float4* w1=(const float4*)(f1w+j*64);
      const float4* xs4=(const float4*)(UH+3584+s2*64);
      #pragma unroll
      for(int i4=0;i4<16;i4++){
        float4 A=w1[i4], X4=xs4[i4];
        a=fmaf(X4.x,A.x,fmaf(X4.y,A.y,fmaf(X4.z,A.z,fmaf(X4.w,A.w,a))));
      }
      UH[4096+idx]=fmaxf(a,0.f);
    }
    __syncthreads();
    // fc2 + residual
    #pragma unroll
    for(int k=0;k<2;k++){
      int idx=tid+k*256;
      int s2=idx>>6, d=idx&63;
      float a=f2b[d];
      const float4* w2=(const float4*)(f2w+d*128);
      const float4* hs4=(const float4*)(UH+4096+s2*128);
      #pragma unroll
      for(int i4=0;i4<32;i4++){
        float4 A=w2[i4], H4=hs4[i4];
        a=fmaf(H4.x,A.x,fmaf(H4.y,A.y,fmaf(H4.z,A.z,fmaf(H4.w,A.w,a))));
      }
      float val=UH[3072+idx]+a;
      slt[idx]=val;
      if(last) out[b*512+idx]=val;
    }
    __syncthreads();
  }
}

extern "C" void kernel_launch(void* const* d_in, const int* in_sizes, int n_in,
                              void* d_out, int out_size){
  const float* inp  =(const float*)d_in[0];
  const float* noise=(const float*)d_in[1];
  const float* mu   =(const float*)d_in[2];
  const float* sig  =(const float*)d_in[3];
  const float* Wq   =(const float*)d_in[4];
  const float* Wk   =(const float*)d_in[5];
  const float* Wv   =(const float*)d_in[6];
  const float* wih  =(const float*)d_in[7];
  const float* whh  =(const float*)d_in[8];
  const float* bih  =(const float*)d_in[9];
  const float* bhh  =(const float*)d_in[10];
  const float* f1w  =(const float*)d_in[11];
  const float* f1b  =(const float*)d_in[12];
  const float* f2w  =(const float*)d_in[13];
  const float* f2b  =(const float*)d_in[14];
  const float* lig  =(const float*)d_in[15];
  const float* lib  =(const float*)d_in[16];
  const float* lsg  =(const float*)d_in[17];
  const float* lsb  =(const float*)d_in[18];
  const float* lfg  =(const float*)d_in[19];
  const float* lfb  =(const float*)d_in[20];
  const float* wiw  =(const float*)d_in[21];
  const float* wib  =(const float*)d_in[22];
  const float* wsw  =(const float*)d_in[23];
  const float* wsb  =(const float*)d_in[24];
  float* out=(float*)d_out;

  cudaFuncSetAttribute(k_main, cudaFuncAttributeMaxDynamicSharedMemorySize, SMEM_BYTES);

  k_prep<<<BB*4,512>>>(inp,lig,lib,Wk,Wv,wiw,wib);
  k_main<<<BB,256,SMEM_BYTES>>>(out,noise,mu,sig,Wq,lsg,lsb,wsw,wsb,
                                wih,whh,bih,bhh,f1w,f1b,f2w,f2b,lfg,lfb);
  (void)in_sizes; (void)n_in; (void)out_size;
}

// round 15
// speedup vs baseline: 1.2647x; 1.0423x over previous
#include <cuda_runtime.h>
#include <cuda_bf16.h>
#include <math.h>

#define BB 256
#define NN 1024
#define NSL 8

typedef unsigned long long u64;

// ---------------- device-global scratch ----------------
__device__ float g_kT[BB*64*NN];   // [b][d][n]
__device__ float g_v[BB*NN*64];    // [b][n][d]
__device__ float g_logits[BB*NN];

__device__ __forceinline__ float wsum(float v){
  #pragma unroll
  for(int o=16;o;o>>=1) v += __shfl_xor_sync(0xffffffffu, v, o);
  return v;
}
__device__ __forceinline__ float wmax(float v){
  #pragma unroll
  for(int o=16;o;o>>=1) v = fmaxf(v, __shfl_xor_sync(0xffffffffu, v, o));
  return v;
}
__device__ __forceinline__ float sigf(float x){ return 1.f/(1.f+__expf(-x)); }
__device__ __forceinline__ float rcpf(float x){
  float r; asm("rcp.approx.ftz.f32 %0,%1;":"=f"(r):"f"(x)); return r;
}
__device__ __forceinline__ int br3(int p){ return ((p&1)<<2)|(p&2)|((p&4)>>2); }

// ---- packed f32x2 helpers ----
__device__ __forceinline__ u64 fpk(float a, float b){
  u64 r; asm("mov.b64 %0,{%1,%2};":"=l"(r):"f"(a),"f"(b)); return r;
}
__device__ __forceinline__ void funpk(u64 p, float& a, float& b){
  asm("mov.b64 {%0,%1},%2;":"=f"(a),"=f"(b):"l"(p));
}
__device__ __forceinline__ u64 fdup(float x){ return fpk(x,x); }
__device__ __forceinline__ u64 pfma(u64 a, u64 b, u64 c){
  u64 d; asm("fma.rn.f32x2 %0,%1,%2,%3;":"=l"(d):"l"(a),"l"(b),"l"(c)); return d;
}
__device__ __forceinline__ u64 pmul(u64 a, u64 b){
  u64 d; asm("mul.rn.f32x2 %0,%1,%2;":"=l"(d):"l"(a),"l"(b)); return d;
}
__device__ __forceinline__ u64 padd(u64 a, u64 b){
  u64 d; asm("add.rn.f32x2 %0,%1,%2;":"=l"(d):"l"(a),"l"(b)); return d;
}

// multi-value butterfly: warp-reduce 8 values in 9 shuffles; returns sum of value br3(l&7).
__device__ __forceinline__ float mred8(const float* c, int l){
  float r1[4], r2[2], r3;
  #pragma unroll
  for(int i=0;i<4;i++){
    float send=(l&1)? c[i] : c[i+4];
    float t=__shfl_xor_sync(0xffffffffu, send, 1);
    r1[i]=((l&1)? c[i+4] : c[i])+t;
  }
  #pragma unroll
  for(int i=0;i<2;i++){
    float send=(l&2)? r1[i] : r1[i+2];
    float t=__shfl_xor_sync(0xffffffffu, send, 2);
    r2[i]=((l&2)? r1[i+2] : r1[i])+t;
  }
  {
    float send=(l&4)? r2[0] : r2[1];
    float t=__shfl_xor_sync(0xffffffffu, send, 4);
    r3=((l&4)? r2[1] : r2[0])+t;
  }
  r3+=__shfl_xor_sync(0xffffffffu, r3, 8);
  r3+=__shfl_xor_sync(0xffffffffu, r3, 16);
  return r3;
}

// ================= k_prep: LN(inputs), k/v proj (packed FMA), wi logits; k TRANSPOSED =================
// grid = 256*4 = 1024, 512 threads, 4 row-blocks each
__global__ void __launch_bounds__(512,3) k_prep(const float* __restrict__ inp,
        const float* __restrict__ lng, const float* __restrict__ lnb,
        const float* __restrict__ Wk, const float* __restrict__ Wv,
        const float* __restrict__ wiw, const float* __restrict__ wib){
  __shared__ float wkT[64*68];
  __shared__ float wvT[64*68];
  __shared__ float xsT[64*68];
  int blk=blockIdx.x;
  int b=blk>>2;
  int tid=threadIdx.x, w=tid>>5, l=tid&31;

  for(int e=tid;e<4096;e+=512){
    int j=e>>6, i=e&63;
    wkT[i*68+j]=Wk[e];
    wvT[i*68+j]=Wv[e];
  }
  __syncthreads();

  for(int bl=0;bl<4;bl++){
    int nb=((blk&3)*4+bl)*64;
    #pragma unroll
    for(int rr=0;rr<4;rr++){
      int row=w*4+rr;
      const float* xr=inp+(size_t)(b*1024+nb+row)*64;
      float x0=xr[l], x1=xr[l+32];
      float s1=wsum(x0+x1), s2=wsum(x0*x0+x1*x1);
      float m=s1*(1.f/64.f), var=s2*(1.f/64.f)-m*m;
      float rs=rsqrtf(var+1e-5f);
      float v0=(x0-m)*rs*lng[l]+lnb[l];
      float v1=(x1-m)*rs*lng[l+32]+lnb[l+32];
      xsT[l*68+row]=v0; xsT[(l+32)*68+row]=v1;
      float lp=wsum(v0*wiw[l]+v1*wiw[l+32]);
      if(l==0) g_logits[b*1024+nb+row]=lp+wib[0];
    }
    __syncthreads();

    int rp=tid&31, j4=(tid>>5)*4;
    u64 kap[2][2]={{0,0},{0,0}}, vap[2][2]={{0,0},{0,0}};
    #pragma unroll 4
    for(int i=0;i<64;i++){
      float2 x2=*(const float2*)&xsT[i*68+rp*2];
      ulonglong2 wk=*(const ulonglong2*)&wkT[i*68+j4];
      ulonglong2 wv=*(const ulonglong2*)&wvT[i*68+j4];
      u64 x0d=fdup(x2.x), x1d=fdup(x2.y);
      kap[0][0]=pfma(x0d,wk.x,kap[0][0]); kap[0][1]=pfma(x0d,wk.y,kap[0][1]);
      kap[1][0]=pfma(x1d,wk.x,kap[1][0]); kap[1][1]=pfma(x1d,wk.y,kap[1][1]);
      vap[0][0]=pfma(x0d,wv.x,vap[0][0]); vap[0][1]=pfma(x0d,wv.y,vap[0][1]);
      vap[1][0]=pfma(x1d,wv.x,vap[1][0]); vap[1][1]=pfma(x1d,wv.y,vap[1][1]);
    }
    float ka[2][4], va[2][4];
    #pragma unroll
    for(int r=0;r<2;r++){
      funpk(kap[r][0],ka[r][0],ka[r][1]); funpk(kap[r][1],ka[r][2],ka[r][3]);
      funpk(vap[r][0],va[r][0],va[r][1]); funpk(vap[r][1],va[r][2],va[r][3]);
    }
    __syncthreads();
    #pragma unroll
    for(int r=0;r<2;r++)
      #pragma unroll
      for(int jj=0;jj<4;jj++)
        xsT[(j4+jj)*68 + rp*2+r]=ka[r][jj];
    __syncthreads();
    #pragma unroll
    for(int q=0;q<8;q++){
      int o=tid+q*512;
      int d=o>>6, n=o&63;
      g_kT[((size_t)b*64+d)*1024 + nb + n]=xsT[d*68+n];
    }
    __syncthreads();
    #pragma unroll
    for(int r=0;r<2;r++)
      #pragma unroll
      for(int jj=0;jj<4;jj++)
        xsT[(rp*2+r)*68 + j4+jj]=va[r][jj];
    __syncthreads();
    #pragma unroll
    for(int q=0;q<8;q++){
      int o=tid+q*512;
      int n=o>>6, d=o&63;
      g_v[((size_t)(b*1024+nb+n))*64 + d]=xsT[n*68+d];
    }
    __syncthreads();
  }
}

// ================= k_main: 256 threads, 4 n/thread; slot dim packed f32x2 =================
#define SO_UH  0       // 8192
#define SO_VT  8192    // 4096
#define SO_QS  12288   // 512 (qsT[d*8+s])
#define SO_SLT 12800   // 512
#define SO_UPD 13312   // 512
#define SO_EVH 13824   // 80
#define SO_EB  13904   // 8
#define SO_EBI 13912   // 8
#define SO_Q2  13920   // 8
#define SO_PS  13936   // 128 (double buffer 2x64, [vv*8+w])
#define SO_EVW 14064   // 64
#define SO_DVW 14128   // 64
#define SO_RED 14192   // 16
#define SM_TOT 14208
#define SMEM_BYTES (SM_TOT*4)

#define OUT_POS  131072
#define OUT_ATTN 135168

__global__ void __launch_bounds__(256,2) k_main(float* __restrict__ out,
  const float* __restrict__ noise, const float* __restrict__ mu, const float* __restrict__ sig,
  const float* __restrict__ Wq,
  const float* __restrict__ lsg, const float* __restrict__ lsb,
  const float* __restrict__ wsw, const float* __restrict__ wsb,
  const float* __restrict__ wih, const float* __restrict__ whh,
  const float* __restrict__ bih, const float* __restrict__ bhh,
  const float* __restrict__ f1w, const float* __restrict__ f1b,
  const float* __restrict__ f2w, const float* __restrict__ f2b,
  const float* __restrict__ lfg, const float* __restrict__ lfb){
  extern __shared__ float sm[];
  float* UH  = sm + SO_UH;
  float* VT  = sm + SO_VT;
  float* qs  = sm + SO_QS;
  float* slt = sm + SO_SLT;
  float* upd = sm + SO_UPD;
  float* EVH = sm + SO_EVH;
  float* eb  = sm + SO_EB;
  float* ebi = sm + SO_EBI;
  float* q2  = sm + SO_Q2;
  float* ps  = sm + SO_PS;
  float* evw = sm + SO_EVW;
  float* dvw = sm + SO_DVW;
  float* red = sm + SO_RED;
  int b=blockIdx.x, tid=threadIdx.x, w=tid>>5, l=tid&31;
  int pbuf=0;
  int n0=2*tid;   // thread n-set: n0, n0+1, n0+512, n0+513
  const u64 ONEPK=0x3F8000003F800000ULL;

  // ---- slots init ----
  #pragma unroll
  for(int k=0;k<2;k++){
    int idx=tid+k*256; int d=idx&63;
    slt[idx]=mu[d]+(fabsf(sig[d])+1e-8f)*noise[b*512+idx];
  }

  // ---- a = softmax(logits)*8 + eps (registers) ----
  float a4[4], ia4[4];
  {
    const float* lg=g_logits+b*1024;
    float2 A=*(const float2*)&lg[n0];
    float2 Bv=*(const float2*)&lg[n0+512];
    float mx=fmaxf(fmaxf(A.x,A.y),fmaxf(Bv.x,Bv.y));
    mx=wmax(mx);
    if(l==0) red[w]=mx;
    __syncthreads();
    float M=-1e30f;
    #pragma unroll
    for(int i=0;i<8;i++) M=fmaxf(M,red[i]);
    float e00=__expf(A.x-M), e01=__expf(A.y-M);
    float e10=__expf(Bv.x-M), e11=__expf(Bv.y-M);
    float ss=wsum(e00+e01+e10+e11);
    if(l==0) ps[w]=ss;
    __syncthreads();
    float S=0.f;
    #pragma unroll
    for(int i=0;i<8;i++) S+=ps[i];
    float invS=8.f/S;
    a4[0]=e00*invS+1e-8f; a4[1]=e01*invS+1e-8f;
    a4[2]=e10*invS+1e-8f; a4[3]=e11*invS+1e-8f;
    #pragma unroll
    for(int i=0;i<4;i++) ia4[i]=rcpf(a4[i]);
  }
  __syncthreads();

  for(int itr=0;itr<3;itr++){
    int last=(itr==2);

    // ---- slotproj: LN(slots) -> UH[0..512), ws logits ----
    {
      float x0=slt[w*64+l], x1=slt[w*64+l+32];
      float s1=wsum(x0+x1), s2=wsum(x0*x0+x1*x1);
      float m=s1*(1.f/64.f), var=s2*(1.f/64.f)-m*m;
      float rs=rsqrtf(var+1e-5f);
      float nn0=(x0-m)*rs*lsg[l]+lsb[l];
      float nn1=(x1-m)*rs*lsg[l+32]+lsb[l+32];
      UH[w*64+l]=nn0; UH[w*64+l+32]=nn1;
      float lp=wsum(nn0*wsw[l]+nn1*wsw[l+32]);
      if(l==0) red[w]=lp+wsb[0];
    }
    __syncthreads();
    if(tid==0){
      float M=red[0];
      for(int i=1;i<8;i++) M=fmaxf(M,red[i]);
      float S=0.f;
      for(int i=0;i<8;i++) S+=__expf(red[i]-M);
      for(int i=0;i<8;i++){
        float bb=8.f*__expf(red[i]-M)/S+1e-8f;
        eb[i]=bb; ebi[i]=rcpf(bb);
      }
    }
    // ---- q projection (2 outputs/thread) -> qsT[d*8+s], |q|^2 ----
    {
      float qv[2]; int sidx[2], didx[2];
      #pragma unroll
      for(int k=0;k<2;k++){
        int idx=tid+k*256;
        int s=idx>>6, d=idx&63;
        sidx[k]=s; didx[k]=d;
        float q=0.f;
        const float4* wq4=(const float4*)(Wq+d*64);
        const float* sns=UH+s*64;
        #pragma unroll
        for(int i4=0;i4<16;i4++){
          float4 ww=wq4[i4];
          q=fmaf(sns[i4*4+0],ww.x,fmaf(sns[i4*4+1],ww.y,fmaf(sns[i4*4+2],ww.z,fmaf(sns[i4*4+3],ww.w,q))));
        }
        qv[k]=q;
        float pq=wsum(q*q);
        if(l==0) ps[k*8+w]=pq;
      }
      __syncthreads();
      qs[didx[0]*8+sidx[0]]=qv[0];
      qs[didx[1]*8+sidx[1]]=qv[1];
      if(tid<8){
        int base=(tid>>2)*8+(tid&3)*2;
        q2[tid]=ps[base]+ps[base+1];
      }
    }
    __syncthreads();

    // ---- cdist -> E packed in registers: Epk[g*4+j] = (E[g][2j], E[g][2j+1]) ----
    u64 Epk[16];
    {
      float q2r[8];
      #pragma unroll
      for(int s=0;s<8;s++) q2r[s]=q2[s];
      u64 dp[16];
      #pragma unroll
      for(int i=0;i<16;i++) dp[i]=0ULL;
      float k2[4]={0.f,0.f,0.f,0.f};
      const float* kTb = g_kT + (size_t)b*65536;
      for(int d=0;d<64;d++){
        ulonglong2 qA=*(const ulonglong2*)&qs[d*8];
        ulonglong2 qB=*(const ulonglong2*)&qs[d*8+4];
        u64 qp[4]={qA.x,qA.y,qB.x,qB.y};
        float2 kA=*(const float2*)&kTb[d*1024 + n0];
        float2 kB=*(const float2*)&kTb[d*1024 + n0 + 512];
        float kv[4]={kA.x,kA.y,kB.x,kB.y};
        #pragma unroll
        for(int g=0;g<4;g++){
          float kk=kv[g];
          k2[g]=fmaf(kk,kk,k2[g]);
          u64 kd=fdup(kk);
          dp[g*4+0]=pfma(kd,qp[0],dp[g*4+0]);
          dp[g*4+1]=pfma(kd,qp[1],dp[g*4+1]);
          dp[g*4+2]=pfma(kd,qp[2],dp[g*4+2]);
          dp[g*4+3]=pfma(kd,qp[3],dp[g*4+3]);
        }
      }
      #pragma unroll
      for(int g=0;g<4;g++)
        #pragma unroll
        for(int j=0;j<4;j++){
          float d0,d1; funpk(dp[g*4+j],d0,d1);
          float e0=__expf(-sqrtf(fmaxf(k2[g]+q2r[2*j]  -2.f*d0,1e-12f)));
          float e1=__expf(-sqrtf(fmaxf(k2[g]+q2r[2*j+1]-2.f*d1,1e-12f)));
          Epk[g*4+j]=fpk(e0,e1);
        }
    }
    __syncthreads();

    // packed 1/(b+eps), constant within this itr
    ulonglong2 biA=*(const ulonglong2*)&ebi[0];
    ulonglong2 biB=*(const ulonglong2*)&ebi[4];
    u64 bip[4]={biA.x,biA.y,biB.x,biB.y};

    // ---- MESH ----
    float du4[4]={0.f,0.f,0.f,0.f};
    float euL[4];
    for(int mesh=0;mesh<4;mesh++){
      if(tid<8) EVH[tid]=1.f;
      __syncthreads();
      // forward
      for(int t=0;t<8;t++){
        u64 evp[4];
        if(t==0){
          evp[0]=evp[1]=evp[2]=evp[3]=ONEPK;
        } else {
          ulonglong2 eA=*(const ulonglong2*)&evw[w*8];
          ulonglong2 eB=*(const ulonglong2*)&evw[w*8+4];
          evp[0]=eA.x; evp[1]=eA.y; evp[2]=eB.x; evp[3]=eB.y;
        }
        u64 colp[4]={0ULL,0ULL,0ULL,0ULL};
        float eu4[4];
        #pragma unroll
        for(int g=0;g<4;g++){
          u64 acc=fpk(1e-38f,0.f);
          acc=pfma(evp[0],Epk[g*4+0],acc);
          acc=pfma(evp[1],Epk[g*4+1],acc);
          acc=pfma(evp[2],Epk[g*4+2],acc);
          acc=pfma(evp[3],Epk[g*4+3],acc);
          float xa,xb; funpk(acc,xa,xb);
          float eu=a4[g]*rcpf(xa+xb);
          eu4[g]=eu;
          if(t==7) euL[g]=eu;
          u64 eup=fdup(eu);
          colp[0]=pfma(eup,Epk[g*4+0],colp[0]);
          colp[1]=pfma(eup,Epk[g*4+1],colp[1]);
          colp[2]=pfma(eup,Epk[g*4+2],colp[2]);
          colp[3]=pfma(eup,Epk[g*4+3],colp[3]);
        }
        *(float2*)&UH[t*1024+n0]    =make_float2(eu4[0],eu4[1]);
        *(float2*)&UH[t*1024+n0+512]=make_float2(eu4[2],eu4[3]);
        float colacc[8];
        funpk(colp[0],colacc[0],colacc[1]);
        funpk(colp[1],colacc[2],colacc[3]);
        funpk(colp[2],colacc[4],colacc[5]);
        funpk(colp[3],colacc[6],colacc[7]);
        float r3=mred8(colacc,l);
        float* pb=ps+(pbuf<<6);
        if(l<8) pb[br3(l)*8+w]=r3;
        __syncthreads();
        if(l<8){
          int vv=br3(l);
          float4 A=*(const float4*)&pb[vv*8];
          float4 Bv=*(const float4*)&pb[vv*8+4];
          float tot=A.x+A.y+A.z+A.w+Bv.x+Bv.y+Bv.z+Bv.w;
          float evv=eb[vv]*rcpf(tot+1e-38f);
          evw[w*8+vv]=evv;
          if(w==0) EVH[(t+1)*8+vv]=evv;
        }
        __syncwarp();
        pbuf^=1;
      }
      // entropy direct terms
      u64 Gpk[16];
      {
        float4 e0=*(const float4*)&evw[w*8];
        float4 e1=*(const float4*)&evw[w*8+4];
        float ev8[8]={e0.x,e0.y,e0.z,e0.w,e1.x,e1.y,e1.z,e1.w};
        float colacc[8];
        #pragma unroll
        for(int s=0;s<8;s++) colacc[s]=0.f;
        #pragma unroll
        for(int g=0;g<4;g++){
          float ra=0.f, eug=euL[g];
          #pragma unroll
          for(int j=0;j<4;j++){
            float E0,E1; funpk(Epk[g*4+j],E0,E1);
            float P0=eug*ev8[2*j]*E0,   P1=eug*ev8[2*j+1]*E1;
            float Pe0=P0+1e-8f,         Pe1=P1+1e-8f;
            float t00=P0*(__logf(Pe0)+P0*rcpf(Pe0));
            float t01=P1*(__logf(Pe1)+P1*rcpf(Pe1));
            Gpk[g*4+j]=fpk(t00,t01);
            ra+=t00+t01;
            colacc[2*j]+=t00; colacc[2*j+1]+=t01;
          }
          du4[g]=-ra;
        }
        float r3=mred8(colacc,l);
        float* pb=ps+(pbuf<<6);
        if(l<8) pb[br3(l)*8+w]=r3;
        __syncthreads();
        if(l<8){
          int vv=br3(l);
          float4 A=*(const float4*)&pb[vv*8];
          float4 Bv=*(const float4*)&pb[vv*8+4];
          dvw[w*8+vv]=-(A.x+A.y+A.z+A.w+Bv.x+Bv.y+Bv.z+Bv.w);
        }
        __syncwarp();
        pbuf^=1;
      }
      // backward t=7..0 (t=0 publishes nothing)
      for(int t=7;t>=0;t--){
        ulonglong2 dA=*(const ulonglong2*)&dvw[w*8];
        ulonglong2 dB=*(const ulonglong2*)&dvw[w*8+4];
        ulonglong2 hA=*(const ulonglong2*)&EVH[(t+1)*8];
        ulonglong2 hB=*(const ulonglong2*)&EVH[(t+1)*8+4];
        u64 wp[4]={pmul(pmul(dA.x,hA.x),bip[0]),
                   pmul(pmul(dA.y,hA.y),bip[1]),
                   pmul(pmul(dB.x,hB.x),bip[2]),
                   pmul(pmul(dB.y,hB.y),bip[3])};
        ulonglong2 mA=*(const ulonglong2*)&EVH[t*8];
        ulonglong2 mB=*(const ulonglong2*)&EVH[t*8+4];
        u64 mp[4]={mA.x,mA.y,mB.x,mB.y};
        float2 uA=*(const float2*)&UH[t*1024+n0];
        float2 uB=*(const float2*)&UH[t*1024+n0+512];
        float ut[4]={uA.x,uA.y,uB.x,uB.y};
        u64 colp[4]={0ULL,0ULL,0ULL,0ULL};
        #pragma unroll
        for(int g=0;g<4;g++){
          u64 t1p=0ULL;
          t1p=pfma(wp[0],Epk[g*4+0],t1p);
          t1p=pfma(wp[1],Epk[g*4+1],t1p);
          t1p=pfma(wp[2],Epk[g*4+2],t1p);
          t1p=pfma(wp[3],Epk[g*4+3],t1p);
          float ta,tb; funpk(t1p,ta,tb);
          float uacc=((t==7)?du4[g]:0.f)-ut[g]*(ta+tb);
          float fun=uacc*ut[g]*ia4[g];
          u64 fd=fdup(fun), ud=fdup(ut[g]);
          #pragma unroll
          for(int j=0;j<4;j++){
            u64 xp=pmul(fd,Epk[g*4+j]);
            colp[j]=padd(colp[j],xp);
            Gpk[g*4+j]=pfma(pmul(Epk[g*4+j],wp[j]),ud,pfma(xp,mp[j],Gpk[g*4+j]));
          }
        }
        if(t>0){
          float colacc[8];
          funpk(colp[0],colacc[0],colacc[1]);
          funpk(colp[1],colacc[2],colacc[3]);
          funpk(colp[2],colacc[4],colacc[5]);
          funpk(colp[3],colacc[6],colacc[7]);
          float r3=mred8(colacc,l);
          float* pb=ps+(pbuf<<6);
          if(l<8) pb[br3(l)*8+w]=r3;
          __syncthreads();
          if(l<8){
            int vv=br3(l);
            float4 A=*(const float4*)&pb[vv*8];
            float4 Bv=*(const float4*)&pb[vv*8+4];
            dvw[w*8+vv]=-EVH[t*8+vv]*(A.x+A.y+A.z+A.w+Bv.x+Bv.y+Bv.z+Bv.w);
          }
          __syncwarp();
          pbuf^=1;
        }
      }
      // E *= exp(3*G)
      #pragma unroll
      for(int p=0;p<16;p++){
        float g0,g1; funpk(Gpk[p],g0,g1);
        Epk[p]=pmul(Epk[p], fpk(__expf(3.0f*g0),__expf(3.0f*g1)));
      }
    }

    // ---- final sinkhorn (warm exp(v)) ----
    for(int it=0;it<8;it++){
      u64 evp[4];
      if(it==0){
        ulonglong2 eA=*(const ulonglong2*)&EVH[64];
        ulonglong2 eB=*(const ulonglong2*)&EVH[68];
        evp[0]=eA.x; evp[1]=eA.y; evp[2]=eB.x; evp[3]=eB.y;
      } else {
        ulonglong2 eA=*(const ulonglong2*)&evw[w*8];
        ulonglong2 eB=*(const ulonglong2*)&evw[w*8+4];
        evp[0]=eA.x; evp[1]=eA.y; evp[2]=eB.x; evp[3]=eB.y;
      }
      u64 colp[4]={0ULL,0ULL,0ULL,0ULL};
      #pragma unroll
      for(int g=0;g<4;g++){
        u64 acc=fpk(1e-38f,0.f);
        acc=pfma(evp[0],Epk[g*4+0],acc);
        acc=pfma(evp[1],Epk[g*4+1],acc);
        acc=pfma(evp[2],Epk[g*4+2],acc);
        acc=pfma(evp[3],Epk[g*4+3],acc);
        float xa,xb; funpk(acc,xa,xb);
        float eu=a4[g]*rcpf(xa+xb);
        if(it==7) euL[g]=eu;
        u64 eup=fdup(eu);
        colp[0]=pfma(eup,Epk[g*4+0],colp[0]);
        colp[1]=pfma(eup,Epk[g*4+1],colp[1]);
        colp[2]=pfma(eup,Epk[g*4+2],colp[2]);
        colp[3]=pfma(eup,Epk[g*4+3],colp[3]);
      }
      float colacc[8];
      funpk(colp[0],colacc[0],colacc[1]);
      funpk(colp[1],colacc[2],colacc[3]);
      funpk(colp[2],colacc[4],colacc[5]);
      funpk(colp[3],colacc[6],colacc[7]);
      float r3=mred8(colacc,l);
      float* pb=ps+(pbuf<<6);
      if(l<8) pb[br3(l)*8+w]=r3;
      __syncthreads();
      if(l<8){
        int vv=br3(l);
        float4 A=*(const float4*)&pb[vv*8];
        float4 Bv=*(const float4*)&pb[vv*8+4];
        evw[w*8+vv]=eb[vv]*rcpf(A.x+A.y+A.z+A.w+Bv.x+Bv.y+Bv.z+Bv.w+1e-38f);
      }
      __syncwarp();
      pbuf^=1;
    }

    // ---- P = EU*EV*E -> UH (and attn out) ----
    {
      float4 e0=*(const float4*)&evw[w*8];
      float4 e1=*(const float4*)&evw[w*8+4];
      float evf[8]={e0.x,e0.y,e0.z,e0.w,e1.x,e1.y,e1.z,e1.w};
      #pragma unroll
      for(int j=0;j<4;j++){
        float E00,E01,E10,E11,E20,E21,E30,E31;
        funpk(Epk[0*4+j],E00,E01);
        funpk(Epk[1*4+j],E10,E11);
        funpk(Epk[2*4+j],E20,E21);
        funpk(Epk[3*4+j],E30,E31);
        int s0=2*j, s1=2*j+1;
        float2 PA0=make_float2(euL[0]*evf[s0]*E00, euL[1]*evf[s0]*E10);
        float2 PB0=make_float2(euL[2]*evf[s0]*E20, euL[3]*evf[s0]*E30);
        float2 PA1=make_float2(euL[0]*evf[s1]*E01, euL[1]*evf[s1]*E11);
        float2 PB1=make_float2(euL[2]*evf[s1]*E21, euL[3]*evf[s1]*E31);
        *(float2*)&UH[s0*1024+n0]    =PA0;
        *(float2*)&UH[s0*1024+n0+512]=PB0;
        *(float2*)&UH[s1*1024+n0]    =PA1;
        *(float2*)&UH[s1*1024+n0+512]=PB1;
        if(last){
          *(float2*)&out[OUT_ATTN+b*8192+s0*1024+n0]    =PA0;
          *(float2*)&out[OUT_ATTN+b*8192+s0*1024+n0+512]=PB0;
          *(float2*)&out[OUT_ATTN+b*8192+s1*1024+n0]    =PA1;
          *(float2*)&out[OUT_ATTN+b*8192+s1*1024+n0+512]=PB1;
        }
      }
    }
    __syncthreads();

    // ---- slot_pos (last): warp w -> slot w ----
    if(last){
      const float* Pp=UH+w*1024;
      float gx=0.f,gy=0.f;
      #pragma unroll 4
      for(int i=l;i<1024;i+=32){
        float p=Pp[i];
        gx=fmaf(p,(float)(i&31),gx);
        gy=fmaf(p,(float)(i>>5),gy);
      }
      gx=wsum(gx); gy=wsum(gy);
      if(l==0){
        out[OUT_POS+(b*8+w)*2+0]=gx*(1.f/31.f);
        out[OUT_POS+(b*8+w)*2+1]=gy*(1.f/31.f);
      }
    }

    // ---- updates = P @ v : split-n, packed, thread -> (half h, s, d-quad) ----
    {
      int h=tid>>7, s=(tid>>4)&7, d4=(tid&15)*4;
      u64 ap0=0ULL, ap1=0ULL;
      const float4* gv4=(const float4*)(g_v+(size_t)b*65536);
      float4* VT4=(float4*)VT;
      for(int t16=0;t16<16;t16++){
        #pragma unroll
        for(int j=0;j<4;j++) VT4[tid+j*256]=gv4[t16*1024+tid+j*256];
        __syncthreads();
        const float* PA=UH+s*1024+t16*64+h*32;
        #pragma unroll 8
        for(int r=0;r<32;r++){
          u64 pd=fdup(PA[r]);
          ulonglong2 v2=*(const ulonglong2*)&VT[(h*32+r)*64+d4];
          ap0=pfma(pd,v2.x,ap0);
          ap1=pfma(pd,v2.y,ap1);
        }
        __syncthreads();
      }
      float o0,o1,o2,o3; funpk(ap0,o0,o1); funpk(ap1,o2,o3);
      float* dst = h ? qs : upd;
      *(float4*)&dst[s*64+d4]=make_float4(o0,o1,o2,o3);
    }
    __syncthreads();
    #pragma unroll
    for(int k=0;k<2;k++){ int idx=tid+k*256; upd[idx]+=qs[idx]; }
    __syncthreads();

    // ---- GRU (scratch in UH), packed dot products ----
    #pragma unroll
    for(int k=0;k<6;k++){
      int idx=tid+k*256;
      int s2=idx/192, j=idx-s2*192;
      u64 ap=0ULL, cp=0ULL;
      const ulonglong2* w1=(const ulonglong2*)(wih+j*64);
      const ulonglong2* w2=(const ulonglong2*)(whh+j*64);
      const ulonglong2* us=(const ulonglong2*)(upd+s2*64);
      const ulonglong2* hs=(const ulonglong2*)(slt+s2*64);
      #pragma unroll
      for(int i4=0;i4<16;i4++){
        ulonglong2 A=w1[i4], Bm=w2[i4], U=us[i4], H=hs[i4];
        ap=pfma(U.x,A.x,ap); ap=pfma(U.y,A.y,ap);
        cp=pfma(H.x,Bm.x,cp); cp=pfma(H.y,Bm.y,cp);
      }
      float ax,ay,cx,cy; funpk(ap,ax,ay); funpk(cp,cx,cy);
      UH[idx]=ax+ay+bih[j]; UH[1536+idx]=cx+cy+bhh[j];
    }
    __syncthreads();
    #pragma unroll
    for(int k=0;k<2;k++){
      int idx=tid+k*256;
      int s2=idx>>6, d=idx&63;
      float r=sigf(UH[s2*192+d]+UH[1536+s2*192+d]);
      float z=sigf(UH[s2*192+64+d]+UH[1536+s2*192+64+d]);
      float nn=tanhf(UH[s2*192+128+d]+r*UH[1536+s2*192+128+d]);
      UH[3072+idx]=(1.f-z)*nn+z*slt[idx];
    }
    __syncthreads();
    // LN(ff)
    {
      float x0=UH[3072+w*64+l], x1=UH[3072+w*64+l+32];
      float s1=wsum(x0+x1), s2=wsum(x0*x0+x1*x1);
      float m=s1*(1.f/64.f), var=s2*(1.f/64.f)-m*m;
      float rs=rsqrtf(var+1e-5f);
      UH[3584+w*64+l]   =(x0-m)*rs*lfg[l]   +lfb[l];
      UH[3584+w*64+l+32]=(x1-m)*rs*lfg[l+32]+lfb[l+32];
    }
    __syncthreads();
    // fc1 (packed)
    #pragma unroll
    for(int k=0;k<4;k++){
      int idx=tid+k*256;
      int s2=idx>>7, j=idx&127;
      u64 ap=0ULL;
      const ulonglong2* w1=(const ulonglong2*)(f1w+j*64);
      const ulonglong2* xs=(const ulonglong2*)(UH+3584+s2*64);
      #pragma unroll
      for(int i4=0;i4<16;i4++){
        ulonglong2 A=w1[i4], X=xs[i4];
        ap=pfma(X.x,A.x,ap); ap=pfma(X.y,A.y,ap);
      }
      float ax,ay; funpk(ap,ax,ay);
      UH[4096+idx]=fmaxf(ax+ay+f1b[j],0.f);
    }
    __syncthreads();
    // fc2 + residual (packed)
    #pragma unroll
    for(int k=0;k<2;k++){
      int idx=tid+k*256;
      int s2=idx>>6, d=idx&63;
      u64 ap=0ULL;
      const ulonglong2* w2=(const ulonglong2*)(f2w+d*128);
      const ulonglong2* hs=(const ulonglong2*)(UH+4096+s2*128);
      #pragma unroll
      for(int i4=0;i4<32;i4++){
        ulonglong2 A=w2[i4], H=hs[i4];
        ap=pfma(H.x,A.x,ap); ap=pfma(H.y,A.y,ap);
      }
      float ax,ay; funpk(ap,ax,ay);
      float val=UH[3072+idx]+ax+ay+f2b[d];
      slt[idx]=val;
      if(last) out[b*512+idx]=val;
    }
    __syncthreads();
  }
}

extern "C" void kernel_launch(void* const* d_in, const int* in_sizes, int n_in,
                              void* d_out, int out_size){
  const float* inp  =(const float*)d_in[0];
  const float* noise=(const float*)d_in[1];
  const float* mu   =(const float*)d_in[2];
  const float* sig  =(const float*)d_in[3];
  const float* Wq   =(const float*)d_in[4];
  const float* Wk   =(const float*)d_in[5];
  const float* Wv   =(const float*)d_in[6];
  const float* wih  =(const float*)d_in[7];
  const float* whh  =(const float*)d_in[8];
  const float* bih  =(const float*)d_in[9];
  const float* bhh  =(const float*)d_in[10];
  const float* f1w  =(const float*)d_in[11];
  const float* f1b  =(const float*)d_in[12];
  const float* f2w  =(const float*)d_in[13];
  const float* f2b  =(const float*)d_in[14];
  const float* lig  =(const float*)d_in[15];
  const float* lib  =(const float*)d_in[16];
  const float* lsg  =(const float*)d_in[17];
  const float* lsb  =(const float*)d_in[18];
  const float* lfg  =(const float*)d_in[19];
  const float* lfb  =(const float*)d_in[20];
  const float* wiw  =(const float*)d_in[21];
  const float* wib  =(const float*)d_in[22];
  const float* wsw  =(const float*)d_in[23];
  const float* wsb  =(const float*)d_in[24];
  float* out=(float*)d_out;

  cudaFuncSetAttribute(k_main, cudaFuncAttributeMaxDynamicSharedMemorySize, SMEM_BYTES);

  k_prep<<<BB*4,512>>>(inp,lig,lib,Wk,Wv,wiw,wib);
  k_main<<<BB,256,SMEM_BYTES>>>(out,noise,mu,sig,Wq,lsg,lsb,wsw,wsb,
                                wih,whh,bih,bhh,f1w,f1b,f2w,f2b,lfg,lfb);
  (void)in_sizes; (void)n_in; (void)out_size;
}

// round 16
// speedup vs baseline: 1.3255x; 1.0481x over previous
#include <cuda_runtime.h>
#include <cuda_bf16.h>
#include <math.h>

#define BB 256
#define NN 1024
#define NSL 8

typedef unsigned long long u64;

// ---------------- device-global scratch ----------------
__device__ float g_kT[BB*64*NN];   // [b][d][n]
__device__ float g_v[BB*NN*64];    // [b][n][d]
__device__ float g_logits[BB*NN];

__device__ __forceinline__ float wsum(float v){
  #pragma unroll
  for(int o=16;o;o>>=1) v += __shfl_xor_sync(0xffffffffu, v, o);
  return v;
}
__device__ __forceinline__ float wmax(float v){
  #pragma unroll
  for(int o=16;o;o>>=1) v = fmaxf(v, __shfl_xor_sync(0xffffffffu, v, o));
  return v;
}
__device__ __forceinline__ float sigf(float x){ return 1.f/(1.f+__expf(-x)); }
__device__ __forceinline__ float rcpf(float x){
  float r; asm("rcp.approx.ftz.f32 %0,%1;":"=f"(r):"f"(x)); return r;
}
__device__ __forceinline__ float ex2f(float x){
  float r; asm("ex2.approx.ftz.f32 %0,%1;":"=f"(r):"f"(x)); return r;
}
__device__ __forceinline__ int br3(int p){ return ((p&1)<<2)|(p&2)|((p&4)>>2); }

// ---- packed f32x2 helpers ----
__device__ __forceinline__ u64 fpk(float a, float b){
  u64 r; asm("mov.b64 %0,{%1,%2};":"=l"(r):"f"(a),"f"(b)); return r;
}
__device__ __forceinline__ void funpk(u64 p, float& a, float& b){
  asm("mov.b64 {%0,%1},%2;":"=f"(a),"=f"(b):"l"(p));
}
__device__ __forceinline__ u64 fdup(float x){ return fpk(x,x); }
__device__ __forceinline__ u64 pfma(u64 a, u64 b, u64 c){
  u64 d; asm("fma.rn.f32x2 %0,%1,%2,%3;":"=l"(d):"l"(a),"l"(b),"l"(c)); return d;
}
__device__ __forceinline__ u64 pmul(u64 a, u64 b){
  u64 d; asm("mul.rn.f32x2 %0,%1,%2;":"=l"(d):"l"(a),"l"(b)); return d;
}

// multi-value butterfly: warp-reduce 8 values in 9 shuffles; returns sum of value br3(l&7).
__device__ __forceinline__ float mred8(const float* c, int l){
  float r1[4], r2[2], r3;
  #pragma unroll
  for(int i=0;i<4;i++){
    float send=(l&1)? c[i] : c[i+4];
    float t=__shfl_xor_sync(0xffffffffu, send, 1);
    r1[i]=((l&1)? c[i+4] : c[i])+t;
  }
  #pragma unroll
  for(int i=0;i<2;i++){
    float send=(l&2)? r1[i] : r1[i+2];
    float t=__shfl_xor_sync(0xffffffffu, send, 2);
    r2[i]=((l&2)? r1[i+2] : r1[i])+t;
  }
  {
    float send=(l&4)? r2[0] : r2[1];
    float t=__shfl_xor_sync(0xffffffffu, send, 4);
    r3=((l&4)? r2[1] : r2[0])+t;
  }
  r3+=__shfl_xor_sync(0xffffffffu, r3, 8);
  r3+=__shfl_xor_sync(0xffffffffu, r3, 16);
  return r3;
}

// ================= k_prep: LN(inputs), k/v proj (packed FMA), wi logits; k TRANSPOSED direct =================
// grid = 256*4 = 1024, 512 threads, 4 row-blocks each
__global__ void __launch_bounds__(512,3) k_prep(const float* __restrict__ inp,
        const float* __restrict__ lng, const float* __restrict__ lnb,
        const float* __restrict__ Wk, const float* __restrict__ Wv,
        const float* __restrict__ wiw, const float* __restrict__ wib){
  __shared__ float wkT[64*68];
  __shared__ float wvT[64*68];
  __shared__ float xsT[64*68];
  int blk=blockIdx.x;
  int b=blk>>2;
  int tid=threadIdx.x, w=tid>>5, l=tid&31;

  for(int e=tid;e<4096;e+=512){
    int j=e>>6, i=e&63;
    wkT[i*68+j]=Wk[e];
    wvT[i*68+j]=Wv[e];
  }
  __syncthreads();

  for(int bl=0;bl<4;bl++){
    int nb=((blk&3)*4+bl)*64;
    #pragma unroll
    for(int rr=0;rr<4;rr++){
      int row=w*4+rr;
      const float* xr=inp+(size_t)(b*1024+nb+row)*64;
      float x0=xr[l], x1=xr[l+32];
      float s1=wsum(x0+x1), s2=wsum(x0*x0+x1*x1);
      float m=s1*(1.f/64.f), var=s2*(1.f/64.f)-m*m;
      float rs=rsqrtf(var+1e-5f);
      float v0=(x0-m)*rs*lng[l]+lnb[l];
      float v1=(x1-m)*rs*lng[l+32]+lnb[l+32];
      xsT[l*68+row]=v0; xsT[(l+32)*68+row]=v1;
      float lp=wsum(v0*wiw[l]+v1*wiw[l+32]);
      if(l==0) g_logits[b*1024+nb+row]=lp+wib[0];
    }
    __syncthreads();

    int rp=tid&31, j4=(tid>>5)*4;
    u64 kap[2][2]={{0,0},{0,0}}, vap[2][2]={{0,0},{0,0}};
    #pragma unroll 4
    for(int i=0;i<64;i++){
      float2 x2=*(const float2*)&xsT[i*68+rp*2];
      ulonglong2 wk=*(const ulonglong2*)&wkT[i*68+j4];
      ulonglong2 wv=*(const ulonglong2*)&wvT[i*68+j4];
      u64 x0d=fdup(x2.x), x1d=fdup(x2.y);
      kap[0][0]=pfma(x0d,wk.x,kap[0][0]); kap[0][1]=pfma(x0d,wk.y,kap[0][1]);
      kap[1][0]=pfma(x1d,wk.x,kap[1][0]); kap[1][1]=pfma(x1d,wk.y,kap[1][1]);
      vap[0][0]=pfma(x0d,wv.x,vap[0][0]); vap[0][1]=pfma(x0d,wv.y,vap[0][1]);
      vap[1][0]=pfma(x1d,wv.x,vap[1][0]); vap[1][1]=pfma(x1d,wv.y,vap[1][1]);
    }
    float ka[2][4], va[2][4];
    #pragma unroll
    for(int r=0;r<2;r++){
      funpk(kap[r][0],ka[r][0],ka[r][1]); funpk(kap[r][1],ka[r][2],ka[r][3]);
      funpk(vap[r][0],va[r][0],va[r][1]); funpk(vap[r][1],va[r][2],va[r][3]);
    }
    // k direct coalesced store: lanes share j4, rows nb+2rp, nb+2rp+1
    {
      size_t kb=((size_t)b*64+j4)*1024 + nb + rp*2;
      #pragma unroll
      for(int jj=0;jj<4;jj++)
        *(float2*)&g_kT[kb + (size_t)jj*1024]=make_float2(ka[0][jj],ka[1][jj]);
    }
    __syncthreads();   // xsT reads done
    // v staging (coalesced via smem)
    #pragma unroll
    for(int r=0;r<2;r++)
      #pragma unroll
      for(int jj=0;jj<4;jj++)
        xsT[(rp*2+r)*68 + j4+jj]=va[r][jj];
    __syncthreads();
    #pragma unroll
    for(int q=0;q<8;q++){
      int o=tid+q*512;
      int n=o>>6, d=o&63;
      g_v[((size_t)(b*1024+nb+n))*64 + d]=xsT[n*68+d];
    }
    __syncthreads();
  }
}

// ================= k_main: 256 threads, 4 n/thread; slot dim packed f32x2 =================
#define SO_UH  0       // 8192
#define SO_VT  8192    // 4096
#define SO_QS  12288   // 512 (qsT[d*8+s])
#define SO_SLT 12800   // 512
#define SO_UPD 13312   // 512
#define SO_EVH 13824   // 80
#define SO_EB  13904   // 8
#define SO_EBI 13912   // 8
#define SO_Q2  13920   // 8
#define SO_PS  13936   // 128 (double buffer 2x64, [vv*8+w])
#define SO_EVW 14064   // 64
#define SO_DVW 14128   // 64
#define SO_RED 14192   // 16
#define SM_TOT 14208
#define SMEM_BYTES (SM_TOT*4)

#define OUT_POS  131072
#define OUT_ATTN 135168

__global__ void __launch_bounds__(256,2) k_main(float* __restrict__ out,
  const float* __restrict__ noise, const float* __restrict__ mu, const float* __restrict__ sig,
  const float* __restrict__ Wq,
  const float* __restrict__ lsg, const float* __restrict__ lsb,
  const float* __restrict__ wsw, const float* __restrict__ wsb,
  const float* __restrict__ wih, const float* __restrict__ whh,
  const float* __restrict__ bih, const float* __restrict__ bhh,
  const float* __restrict__ f1w, const float* __restrict__ f1b,
  const float* __restrict__ f2w, const float* __restrict__ f2b,
  const float* __restrict__ lfg, const float* __restrict__ lfb){
  extern __shared__ float sm[];
  float* UH  = sm + SO_UH;
  float* VT  = sm + SO_VT;
  float* qs  = sm + SO_QS;
  float* slt = sm + SO_SLT;
  float* upd = sm + SO_UPD;
  float* EVH = sm + SO_EVH;
  float* eb  = sm + SO_EB;
  float* ebi = sm + SO_EBI;
  float* q2  = sm + SO_Q2;
  float* ps  = sm + SO_PS;
  float* evw = sm + SO_EVW;
  float* dvw = sm + SO_DVW;
  float* red = sm + SO_RED;
  int b=blockIdx.x, tid=threadIdx.x, w=tid>>5, l=tid&31;
  int pbuf=0;
  int n0=2*tid;   // thread n-set: n0, n0+1, n0+512, n0+513
  const u64 ONEPK=0x3F8000003F800000ULL;

  // ---- slots init ----
  #pragma unroll
  for(int k=0;k<2;k++){
    int idx=tid+k*256; int d=idx&63;
    slt[idx]=mu[d]+(fabsf(sig[d])+1e-8f)*noise[b*512+idx];
  }

  // ---- a = softmax(logits)*8 + eps (registers) ----
  float a4[4], ia4[4];
  {
    const float* lg=g_logits+b*1024;
    float2 A=*(const float2*)&lg[n0];
    float2 Bv=*(const float2*)&lg[n0+512];
    float mx=fmaxf(fmaxf(A.x,A.y),fmaxf(Bv.x,Bv.y));
    mx=wmax(mx);
    if(l==0) red[w]=mx;
    __syncthreads();
    float M=-1e30f;
    #pragma unroll
    for(int i=0;i<8;i++) M=fmaxf(M,red[i]);
    float e00=__expf(A.x-M), e01=__expf(A.y-M);
    float e10=__expf(Bv.x-M), e11=__expf(Bv.y-M);
    float ss=wsum(e00+e01+e10+e11);
    if(l==0) ps[w]=ss;
    __syncthreads();
    float S=0.f;
    #pragma unroll
    for(int i=0;i<8;i++) S+=ps[i];
    float invS=8.f/S;
    a4[0]=e00*invS+1e-8f; a4[1]=e01*invS+1e-8f;
    a4[2]=e10*invS+1e-8f; a4[3]=e11*invS+1e-8f;
    #pragma unroll
    for(int i=0;i<4;i++) ia4[i]=rcpf(a4[i]);
  }
  __syncthreads();

  for(int itr=0;itr<3;itr++){
    int last=(itr==2);

    // ---- slotproj: LN(slots) -> UH[0..512), ws logits ----
    {
      float x0=slt[w*64+l], x1=slt[w*64+l+32];
      float s1=wsum(x0+x1), s2=wsum(x0*x0+x1*x1);
      float m=s1*(1.f/64.f), var=s2*(1.f/64.f)-m*m;
      float rs=rsqrtf(var+1e-5f);
      float nn0=(x0-m)*rs*lsg[l]+lsb[l];
      float nn1=(x1-m)*rs*lsg[l+32]+lsb[l+32];
      UH[w*64+l]=nn0; UH[w*64+l+32]=nn1;
      float lp=wsum(nn0*wsw[l]+nn1*wsw[l+32]);
      if(l==0) red[w]=lp+wsb[0];
    }
    __syncthreads();
    if(tid==0){
      float M=red[0];
      for(int i=1;i<8;i++) M=fmaxf(M,red[i]);
      float S=0.f;
      for(int i=0;i<8;i++) S+=__expf(red[i]-M);
      for(int i=0;i<8;i++){
        float bb=8.f*__expf(red[i]-M)/S+1e-8f;
        eb[i]=bb; ebi[i]=rcpf(bb);
      }
    }
    // ---- q projection (2 outputs/thread) -> qsT[d*8+s], |q|^2 ----
    {
      float qv[2]; int sidx[2], didx[2];
      #pragma unroll
      for(int k=0;k<2;k++){
        int idx=tid+k*256;
        int s=idx>>6, d=idx&63;
        sidx[k]=s; didx[k]=d;
        float q=0.f;
        const float4* wq4=(const float4*)(Wq+d*64);
        const float* sns=UH+s*64;
        #pragma unroll
        for(int i4=0;i4<16;i4++){
          float4 ww=wq4[i4];
          q=fmaf(sns[i4*4+0],ww.x,fmaf(sns[i4*4+1],ww.y,fmaf(sns[i4*4+2],ww.z,fmaf(sns[i4*4+3],ww.w,q))));
        }
        qv[k]=q;
        float pq=wsum(q*q);
        if(l==0) ps[k*8+w]=pq;
      }
      __syncthreads();
      qs[didx[0]*8+sidx[0]]=qv[0];
      qs[didx[1]*8+sidx[1]]=qv[1];
      if(tid<8){
        int base=(tid>>2)*8+(tid&3)*2;
        q2[tid]=ps[base]+ps[base+1];
      }
    }
    __syncthreads();

    // ---- cdist -> E packed in registers: Epk[g*4+j] = (E[g][2j], E[g][2j+1]) ----
    u64 Epk[16];
    {
      float q2r[8];
      #pragma unroll
      for(int s=0;s<8;s++) q2r[s]=q2[s];
      u64 dp[16];
      #pragma unroll
      for(int i=0;i<16;i++) dp[i]=0ULL;
      u64 k2p[2]={0ULL,0ULL};
      const float* kTb = g_kT + (size_t)b*65536;
      for(int d=0;d<64;d++){
        ulonglong2 qA=*(const ulonglong2*)&qs[d*8];
        ulonglong2 qB=*(const ulonglong2*)&qs[d*8+4];
        u64 qp[4]={qA.x,qA.y,qB.x,qB.y};
        float2 kA=*(const float2*)&kTb[d*1024 + n0];
        float2 kB=*(const float2*)&kTb[d*1024 + n0 + 512];
        u64 kApk=fpk(kA.x,kA.y), kBpk=fpk(kB.x,kB.y);
        k2p[0]=pfma(kApk,kApk,k2p[0]);
        k2p[1]=pfma(kBpk,kBpk,k2p[1]);
        float kv[4]={kA.x,kA.y,kB.x,kB.y};
        #pragma unroll
        for(int g=0;g<4;g++){
          u64 kd=fdup(kv[g]);
          dp[g*4+0]=pfma(kd,qp[0],dp[g*4+0]);
          dp[g*4+1]=pfma(kd,qp[1],dp[g*4+1]);
          dp[g*4+2]=pfma(kd,qp[2],dp[g*4+2]);
          dp[g*4+3]=pfma(kd,qp[3],dp[g*4+3]);
        }
      }
      float k2[4];
      funpk(k2p[0],k2[0],k2[1]);
      funpk(k2p[1],k2[2],k2[3]);
      #pragma unroll
      for(int g=0;g<4;g++)
        #pragma unroll
        for(int j=0;j<4;j++){
          float d0,d1; funpk(dp[g*4+j],d0,d1);
          float e0=__expf(-sqrtf(fmaxf(k2[g]+q2r[2*j]  -2.f*d0,1e-12f)));
          float e1=__expf(-sqrtf(fmaxf(k2[g]+q2r[2*j+1]-2.f*d1,1e-12f)));
          Epk[g*4+j]=fpk(e0,e1);
        }
    }
    __syncthreads();

    // packed 1/(b+eps), constant within this itr
    ulonglong2 biA=*(const ulonglong2*)&ebi[0];
    ulonglong2 biB=*(const ulonglong2*)&ebi[4];
    u64 bip[4]={biA.x,biA.y,biB.x,biB.y};

    // ---- MESH ----
    float du4[4]={0.f,0.f,0.f,0.f};
    float euL[4];
    for(int mesh=0;mesh<4;mesh++){
      if(tid<8) EVH[tid]=1.f;
      __syncthreads();
      // forward
      for(int t=0;t<8;t++){
        u64 evp[4];
        if(t==0){
          evp[0]=evp[1]=evp[2]=evp[3]=ONEPK;
        } else {
          ulonglong2 eA=*(const ulonglong2*)&evw[w*8];
          ulonglong2 eB=*(const ulonglong2*)&evw[w*8+4];
          evp[0]=eA.x; evp[1]=eA.y; evp[2]=eB.x; evp[3]=eB.y;
        }
        u64 colp[4]={0ULL,0ULL,0ULL,0ULL};
        float eu4[4];
        #pragma unroll
        for(int g=0;g<4;g++){
          u64 acc=fpk(1e-38f,0.f);
          acc=pfma(evp[0],Epk[g*4+0],acc);
          acc=pfma(evp[1],Epk[g*4+1],acc);
          acc=pfma(evp[2],Epk[g*4+2],acc);
          acc=pfma(evp[3],Epk[g*4+3],acc);
          float xa,xb; funpk(acc,xa,xb);
          float eu=a4[g]*rcpf(xa+xb);
          eu4[g]=eu;
          if(t==7) euL[g]=eu;
          u64 eup=fdup(eu);
          colp[0]=pfma(eup,Epk[g*4+0],colp[0]);
          colp[1]=pfma(eup,Epk[g*4+1],colp[1]);
          colp[2]=pfma(eup,Epk[g*4+2],colp[2]);
          colp[3]=pfma(eup,Epk[g*4+3],colp[3]);
        }
        *(float2*)&UH[t*1024+n0]    =make_float2(eu4[0],eu4[1]);
        *(float2*)&UH[t*1024+n0+512]=make_float2(eu4[2],eu4[3]);
        float colacc[8];
        funpk(colp[0],colacc[0],colacc[1]);
        funpk(colp[1],colacc[2],colacc[3]);
        funpk(colp[2],colacc[4],colacc[5]);
        funpk(colp[3],colacc[6],colacc[7]);
        float r3=mred8(colacc,l);
        float* pb=ps+(pbuf<<6);
        if(l<8) pb[br3(l)*8+w]=r3;
        __syncthreads();
        if(l<8){
          int vv=br3(l);
          float4 A=*(const float4*)&pb[vv*8];
          float4 Bv=*(const float4*)&pb[vv*8+4];
          float tot=A.x+A.y+A.z+A.w+Bv.x+Bv.y+Bv.z+Bv.w;
          float evv=eb[vv]*rcpf(tot+1e-38f);
          evw[w*8+vv]=evv;
          if(w==0) EVH[(t+1)*8+vv]=evv;
        }
        __syncwarp();
        pbuf^=1;
      }
      // entropy direct terms
      u64 Gpk[16];
      {
        float4 e0=*(const float4*)&evw[w*8];
        float4 e1=*(const float4*)&evw[w*8+4];
        float ev8[8]={e0.x,e0.y,e0.z,e0.w,e1.x,e1.y,e1.z,e1.w};
        float colacc[8];
        #pragma unroll
        for(int s=0;s<8;s++) colacc[s]=0.f;
        #pragma unroll
        for(int g=0;g<4;g++){
          float ra=0.f, eug=euL[g];
          #pragma unroll
          for(int j=0;j<4;j++){
            float E0,E1; funpk(Epk[g*4+j],E0,E1);
            float P0=eug*ev8[2*j]*E0,   P1=eug*ev8[2*j+1]*E1;
            float Pe0=P0+1e-8f,         Pe1=P1+1e-8f;
            float t00=P0*(__logf(Pe0)+P0*rcpf(Pe0));
            float t01=P1*(__logf(Pe1)+P1*rcpf(Pe1));
            Gpk[g*4+j]=fpk(t00,t01);
            ra+=t00+t01;
            colacc[2*j]+=t00; colacc[2*j+1]+=t01;
          }
          du4[g]=-ra;
        }
        float r3=mred8(colacc,l);
        float* pb=ps+(pbuf<<6);
        if(l<8) pb[br3(l)*8+w]=r3;
        __syncthreads();
        if(l<8){
          int vv=br3(l);
          float4 A=*(const float4*)&pb[vv*8];
          float4 Bv=*(const float4*)&pb[vv*8+4];
          dvw[w*8+vv]=-(A.x+A.y+A.z+A.w+Bv.x+Bv.y+Bv.z+Bv.w);
        }
        __syncwarp();
        pbuf^=1;
      }
      // backward t=7..0 (t=0 publishes nothing); EVH row t+1 carried in regs
      u64 hp[4];
      {
        ulonglong2 hA=*(const ulonglong2*)&EVH[64];
        ulonglong2 hB=*(const ulonglong2*)&EVH[68];
        hp[0]=hA.x; hp[1]=hA.y; hp[2]=hB.x; hp[3]=hB.y;
      }
      for(int t=7;t>=0;t--){
        ulonglong2 dA=*(const ulonglong2*)&dvw[w*8];
        ulonglong2 dB=*(const ulonglong2*)&dvw[w*8+4];
        u64 wp[4]={pmul(pmul(dA.x,hp[0]),bip[0]),
                   pmul(pmul(dA.y,hp[1]),bip[1]),
                   pmul(pmul(dB.x,hp[2]),bip[2]),
                   pmul(pmul(dB.y,hp[3]),bip[3])};
        ulonglong2 mA=*(const ulonglong2*)&EVH[t*8];
        ulonglong2 mB=*(const ulonglong2*)&EVH[t*8+4];
        u64 mpk[4]={mA.x,mA.y,mB.x,mB.y};
        float2 uA=*(const float2*)&UH[t*1024+n0];
        float2 uB=*(const float2*)&UH[t*1024+n0+512];
        float ut[4]={uA.x,uA.y,uB.x,uB.y};
        u64 colp[4]={0ULL,0ULL,0ULL,0ULL};
        #pragma unroll
        for(int g=0;g<4;g++){
          u64 t1p=0ULL;
          t1p=pfma(wp[0],Epk[g*4+0],t1p);
          t1p=pfma(wp[1],Epk[g*4+1],t1p);
          t1p=pfma(wp[2],Epk[g*4+2],t1p);
          t1p=pfma(wp[3],Epk[g*4+3],t1p);
          float ta,tb; funpk(t1p,ta,tb);
          float uacc=((t==7)?du4[g]:0.f)-ut[g]*(ta+tb);
          float fun=uacc*ut[g]*ia4[g];
          u64 fd=fdup(fun), ud=fdup(ut[g]);
          #pragma unroll
          for(int j=0;j<4;j++){
            u64 inner=pfma(ud,wp[j],pmul(fd,mpk[j]));
            Gpk[g*4+j]=pfma(Epk[g*4+j],inner,Gpk[g*4+j]);
            colp[j]=pfma(fd,Epk[g*4+j],colp[j]);
          }
        }
        if(t>0){
          float colacc[8];
          funpk(colp[0],colacc[0],colacc[1]);
          funpk(colp[1],colacc[2],colacc[3]);
          funpk(colp[2],colacc[4],colacc[5]);
          funpk(colp[3],colacc[6],colacc[7]);
          float r3=mred8(colacc,l);
          float* pb=ps+(pbuf<<6);
          if(l<8) pb[br3(l)*8+w]=r3;
          __syncthreads();
          if(l<8){
            int vv=br3(l);
            float4 A=*(const float4*)&pb[vv*8];
            float4 Bv=*(const float4*)&pb[vv*8+4];
            dvw[w*8+vv]=-EVH[t*8+vv]*(A.x+A.y+A.z+A.w+Bv.x+Bv.y+Bv.z+Bv.w);
          }
          __syncwarp();
          pbuf^=1;
        }
        hp[0]=mpk[0]; hp[1]=mpk[1]; hp[2]=mpk[2]; hp[3]=mpk[3];
      }
      // E *= exp(3*G) via packed pre-scale + ex2
      {
        const u64 C3L=fdup(3.0f*1.4426950408889634f);
        #pragma unroll
        for(int p=0;p<16;p++){
          u64 gl=pmul(Gpk[p],C3L);
          float g0,g1; funpk(gl,g0,g1);
          Epk[p]=pmul(Epk[p], fpk(ex2f(g0),ex2f(g1)));
        }
      }
    }

    // ---- final sinkhorn (warm exp(v)) ----
    for(int it=0;it<8;it++){
      u64 evp[4];
      if(it==0){
        ulonglong2 eA=*(const ulonglong2*)&EVH[64];
        ulonglong2 eB=*(const ulonglong2*)&EVH[68];
        evp[0]=eA.x; evp[1]=eA.y; evp[2]=eB.x; evp[3]=eB.y;
      } else {
        ulonglong2 eA=*(const ulonglong2*)&evw[w*8];
        ulonglong2 eB=*(const ulonglong2*)&evw[w*8+4];
        evp[0]=eA.x; evp[1]=eA.y; evp[2]=eB.x; evp[3]=eB.y;
      }
      u64 colp[4]={0ULL,0ULL,0ULL,0ULL};
      #pragma unroll
      for(int g=0;g<4;g++){
        u64 acc=fpk(1e-38f,0.f);
        acc=pfma(evp[0],Epk[g*4+0],acc);
        acc=pfma(evp[1],Epk[g*4+1],acc);
        acc=pfma(evp[2],Epk[g*4+2],acc);
        acc=pfma(evp[3],Epk[g*4+3],acc);
        float xa,xb; funpk(acc,xa,xb);
        float eu=a4[g]*rcpf(xa+xb);
        if(it==7) euL[g]=eu;
        u64 eup=fdup(eu);
        colp[0]=pfma(eup,Epk[g*4+0],colp[0]);
        colp[1]=pfma(eup,Epk[g*4+1],colp[1]);
        colp[2]=pfma(eup,Epk[g*4+2],colp[2]);
        colp[3]=pfma(eup,Epk[g*4+3],colp[3]);
      }
      float colacc[8];
      funpk(colp[0],colacc[0],colacc[1]);
      funpk(colp[1],colacc[2],colacc[3]);
      funpk(colp[2],colacc[4],colacc[5]);
      funpk(colp[3],colacc[6],colacc[7]);
      float r3=mred8(colacc,l);
      float* pb=ps+(pbuf<<6);
      if(l<8) pb[br3(l)*8+w]=r3;
      __syncthreads();
      if(l<8){
        int vv=br3(l);
        float4 A=*(const float4*)&pb[vv*8];
        float4 Bv=*(const float4*)&pb[vv*8+4];
        evw[w*8+vv]=eb[vv]*rcpf(A.x+A.y+A.z+A.w+Bv.x+Bv.y+Bv.z+Bv.w+1e-38f);
      }
      __syncwarp();
      pbuf^=1;
    }

    // ---- P = EU*EV*E -> UH (and attn out) ----
    {
      float4 e0=*(const float4*)&evw[w*8];
      float4 e1=*(const float4*)&evw[w*8+4];
      float evf[8]={e0.x,e0.y,e0.z,e0.w,e1.x,e1.y,e1.z,e1.w};
      #pragma unroll
      for(int j=0;j<4;j++){
        float E00,E01,E10,E11,E20,E21,E30,E31;
        funpk(Epk[0*4+j],E00,E01);
        funpk(Epk[1*4+j],E10,E11);
        funpk(Epk[2*4+j],E20,E21);
        funpk(Epk[3*4+j],E30,E31);
        int s0=2*j, s1=2*j+1;
        float2 PA0=make_float2(euL[0]*evf[s0]*E00, euL[1]*evf[s0]*E10);
        float2 PB0=make_float2(euL[2]*evf[s0]*E20, euL[3]*evf[s0]*E30);
        float2 PA1=make_float2(euL[0]*evf[s1]*E01, euL[1]*evf[s1]*E11);
        float2 PB1=make_float2(euL[2]*evf[s1]*E21, euL[3]*evf[s1]*E31);
        *(float2*)&UH[s0*1024+n0]    =PA0;
        *(float2*)&UH[s0*1024+n0+512]=PB0;
        *(float2*)&UH[s1*1024+n0]    =PA1;
        *(float2*)&UH[s1*1024+n0+512]=PB1;
        if(last){
          *(float2*)&out[OUT_ATTN+b*8192+s0*1024+n0]    =PA0;
          *(float2*)&out[OUT_ATTN+b*8192+s0*1024+n0+512]=PB0;
          *(float2*)&out[OUT_ATTN+b*8192+s1*1024+n0]    =PA1;
          *(float2*)&out[OUT_ATTN+b*8192+s1*1024+n0+512]=PB1;
        }
      }
    }
    __syncthreads();

    // ---- slot_pos (last): warp w -> slot w ----
    if(last){
      const float* Pp=UH+w*1024;
      float gx=0.f,gy=0.f;
      #pragma unroll 4
      for(int i=l;i<1024;i+=32){
        float p=Pp[i];
        gx=fmaf(p,(float)(i&31),gx);
        gy=fmaf(p,(float)(i>>5),gy);
      }
      gx=wsum(gx); gy=wsum(gy);
      if(l==0){
        out[OUT_POS+(b*8+w)*2+0]=gx*(1.f/31.f);
        out[OUT_POS+(b*8+w)*2+1]=gy*(1.f/31.f);
      }
    }

    // ---- updates = P @ v : split-n, packed, thread -> (half h, s, d-quad) ----
    {
      int h=tid>>7, s=(tid>>4)&7, d4=(tid&15)*4;
      u64 ap0=0ULL, ap1=0ULL;
      const float4* gv4=(const float4*)(g_v+(size_t)b*65536);
      float4* VT4=(float4*)VT;
      for(int t16=0;t16<16;t16++){
        #pragma unroll
        for(int j=0;j<4;j++) VT4[tid+j*256]=gv4[t16*1024+tid+j*256];
        __syncthreads();
        const float* PA=UH+s*1024+t16*64+h*32;
        #pragma unroll 8
        for(int r=0;r<32;r++){
          u64 pd=fdup(PA[r]);
          ulonglong2 v2=*(const ulonglong2*)&VT[(h*32+r)*64+d4];
          ap0=pfma(pd,v2.x,ap0);
          ap1=pfma(pd,v2.y,ap1);
        }
        __syncthreads();
      }
      float o0,o1,o2,o3; funpk(ap0,o0,o1); funpk(ap1,o2,o3);
      float* dst = h ? qs : upd;
      *(float4*)&dst[s*64+d4]=make_float4(o0,o1,o2,o3);
    }
    __syncthreads();
    #pragma unroll
    for(int k=0;k<2;k++){ int idx=tid+k*256; upd[idx]+=qs[idx]; }
    __syncthreads();

    // ---- GRU (scratch in UH), packed dot products ----
    #pragma unroll
    for(int k=0;k<6;k++){
      int idx=tid+k*256;
      int s2=idx/192, j=idx-s2*192;
      u64 ap=0ULL, cp=0ULL;
      const ulonglong2* w1=(const ulonglong2*)(wih+j*64);
      const ulonglong2* w2=(const ulonglong2*)(whh+j*64);
      const ulonglong2* us=(const ulonglong2*)(upd+s2*64);
      const ulonglong2* hs=(const ulonglong2*)(slt+s2*64);
      #pragma unroll
      for(int i4=0;i4<16;i4++){
        ulonglong2 A=w1[i4], Bm=w2[i4], U=us[i4], H=hs[i4];
        ap=pfma(U.x,A.x,ap); ap=pfma(U.y,A.y,ap);
        cp=pfma(H.x,Bm.x,cp); cp=pfma(H.y,Bm.y,cp);
      }
      float ax,ay,cx,cy; funpk(ap,ax,ay); funpk(cp,cx,cy);
      UH[idx]=ax+ay+bih[j]; UH[1536+idx]=cx+cy+bhh[j];
    }
    __syncthreads();
    #pragma unroll
    for(int k=0;k<2;k++){
      int idx=tid+k*256;
      int s2=idx>>6, d=idx&63;
      float r=sigf(UH[s2*192+d]+UH[1536+s2*192+d]);
      float z=sigf(UH[s2*192+64+d]+UH[1536+s2*192+64+d]);
      float nn=tanhf(UH[s2*192+128+d]+r*UH[1536+s2*192+128+d]);
      UH[3072+idx]=(1.f-z)*nn+z*slt[idx];
    }
    __syncthreads();
    // LN(ff)
    {
      float x0=UH[3072+w*64+l], x1=UH[3072+w*64+l+32];
      float s1=wsum(x0+x1), s2=wsum(x0*x0+x1*x1);
      float m=s1*(1.f/64.f), var=s2*(1.f/64.f)-m*m;
      float rs=rsqrtf(var+1e-5f);
      UH[3584+w*64+l]   =(x0-m)*rs*lfg[l]   +lfb[l];
      UH[3584+w*64+l+32]=(x1-m)*rs*lfg[l+32]+lfb[l+32];
    }
    __syncthreads();
    // fc1 (packed)
    #pragma unroll
    for(int k=0;k<4;k++){
      int idx=tid+k*256;
      int s2=idx>>7, j=idx&127;
      u64 ap=0ULL;
      const ulonglong2* w1=(const ulonglong2*)(f1w+j*64);
      const ulonglong2* xs=(const ulonglong2*)(UH+3584+s2*64);
      #pragma unroll
      for(int i4=0;i4<16;i4++){
        ulonglong2 A=w1[i4], X=xs[i4];
        ap=pfma(X.x,A.x,ap); ap=pfma(X.y,A.y,ap);
      }
      float ax,ay; funpk(ap,ax,ay);
      UH[4096+idx]=fmaxf(ax+ay+f1b[j],0.f);
    }
    __syncthreads();
    // fc2 + residual (packed)
    #pragma unroll
    for(int k=0;k<2;k++){
      int idx=tid+k*256;
      int s2=idx>>6, d=idx&63;
      u64 ap=0ULL;
      const ulonglong2* w2=(const ulonglong2*)(f2w+d*128);
      const ulonglong2* hs=(const ulonglong2*)(UH+4096+s2*128);
      #pragma unroll
      for(int i4=0;i4<32;i4++){
        ulonglong2 A=w2[i4], H=hs[i4];
        ap=pfma(H.x,A.x,ap); ap=pfma(H.y,A.y,ap);
      }
      float ax,ay; funpk(ap,ax,ay);
      float val=UH[3072+idx]+ax+ay+f2b[d];
      slt[idx]=val;
      if(last) out[b*512+idx]=val;
    }
    __syncthreads();
  }
}

extern "C" void kernel_launch(void* const* d_in, const int* in_sizes, int n_in,
                              void* d_out, int out_size){
  const float* inp  =(const float*)d_in[0];
  const float* noise=(const float*)d_in[1];
  const float* mu   =(const float*)d_in[2];
  const float* sig  =(const float*)d_in[3];
  const float* Wq   =(const float*)d_in[4];
  const float* Wk   =(const float*)d_in[5];
  const float* Wv   =(const float*)d_in[6];
  const float* wih  =(const float*)d_in[7];
  const float* whh  =(const float*)d_in[8];
  const float* bih  =(const float*)d_in[9];
  const float* bhh  =(const float*)d_in[10];
  const float* f1w  =(const float*)d_in[11];
  const float* f1b  =(const float*)d_in[12];
  const float* f2w  =(const float*)d_in[13];
  const float* f2b  =(const float*)d_in[14];
  const float* lig  =(const float*)d_in[15];
  const float* lib  =(const float*)d_in[16];
  const float* lsg  =(const float*)d_in[17];
  const float* lsb  =(const float*)d_in[18];
  const float* lfg  =(const float*)d_in[19];
  const float* lfb  =(const float*)d_in[20];
  const float* wiw  =(const float*)d_in[21];
  const float* wib  =(const float*)d_in[22];
  const float* wsw  =(const float*)d_in[23];
  const float* wsb  =(const float*)d_in[24];
  float* out=(float*)d_out;

  cudaFuncSetAttribute(k_main, cudaFuncAttributeMaxDynamicSharedMemorySize, SMEM_BYTES);

  k_prep<<<BB*4,512>>>(inp,lig,lib,Wk,Wv,wiw,wib);
  k_main<<<BB,256,SMEM_BYTES>>>(out,noise,mu,sig,Wq,lsg,lsb,wsw,wsb,
                                wih,whh,bih,bhh,f1w,f1b,f2w,f2b,lfg,lfb);
  (void)in_sizes; (void)n_in; (void)out_size;
}

// round 17
// speedup vs baseline: 1.3828x; 1.0433x over previous
#include <cuda_runtime.h>
#include <cuda_bf16.h>
#include <math.h>

#define BB 256
#define NN 1024
#define NSL 8

typedef unsigned long long u64;

// ---------------- device-global scratch ----------------
__device__ float g_kT[BB*64*NN];   // [b][d][n]
__device__ float g_x[BB*NN*64];    // [b][n][d]  (LN'd inputs xn; v = xn @ Wv^T applied late)
__device__ float g_logits[BB*NN];

__device__ __forceinline__ float wsum(float v){
  #pragma unroll
  for(int o=16;o;o>>=1) v += __shfl_xor_sync(0xffffffffu, v, o);
  return v;
}
__device__ __forceinline__ float wmax(float v){
  #pragma unroll
  for(int o=16;o;o>>=1) v = fmaxf(v, __shfl_xor_sync(0xffffffffu, v, o));
  return v;
}
__device__ __forceinline__ float sigf(float x){ return 1.f/(1.f+__expf(-x)); }
__device__ __forceinline__ float rcpf(float x){
  float r; asm("rcp.approx.ftz.f32 %0,%1;":"=f"(r):"f"(x)); return r;
}
__device__ __forceinline__ float ex2f(float x){
  float r; asm("ex2.approx.ftz.f32 %0,%1;":"=f"(r):"f"(x)); return r;
}
__device__ __forceinline__ int br3(int p){ return ((p&1)<<2)|(p&2)|((p&4)>>2); }

// ---- packed f32x2 helpers ----
__device__ __forceinline__ u64 fpk(float a, float b){
  u64 r; asm("mov.b64 %0,{%1,%2};":"=l"(r):"f"(a),"f"(b)); return r;
}
__device__ __forceinline__ void funpk(u64 p, float& a, float& b){
  asm("mov.b64 {%0,%1},%2;":"=f"(a),"=f"(b):"l"(p));
}
__device__ __forceinline__ u64 fdup(float x){ return fpk(x,x); }
__device__ __forceinline__ u64 pfma(u64 a, u64 b, u64 c){
  u64 d; asm("fma.rn.f32x2 %0,%1,%2,%3;":"=l"(d):"l"(a),"l"(b),"l"(c)); return d;
}
__device__ __forceinline__ u64 pmul(u64 a, u64 b){
  u64 d; asm("mul.rn.f32x2 %0,%1,%2;":"=l"(d):"l"(a),"l"(b)); return d;
}

// multi-value butterfly: warp-reduce 8 values in 9 shuffles; returns sum of value br3(l&7).
__device__ __forceinline__ float mred8(const float* c, int l){
  float r1[4], r2[2], r3;
  #pragma unroll
  for(int i=0;i<4;i++){
    float send=(l&1)? c[i] : c[i+4];
    float t=__shfl_xor_sync(0xffffffffu, send, 1);
    r1[i]=((l&1)? c[i+4] : c[i])+t;
  }
  #pragma unroll
  for(int i=0;i<2;i++){
    float send=(l&2)? r1[i] : r1[i+2];
    float t=__shfl_xor_sync(0xffffffffu, send, 2);
    r2[i]=((l&2)? r1[i+2] : r1[i])+t;
  }
  {
    float send=(l&4)? r2[0] : r2[1];
    float t=__shfl_xor_sync(0xffffffffu, send, 4);
    r3=((l&4)? r2[1] : r2[0])+t;
  }
  r3+=__shfl_xor_sync(0xffffffffu, r3, 8);
  r3+=__shfl_xor_sync(0xffffffffu, r3, 16);
  return r3;
}

// ================= k_prep: LN(inputs), k proj only (packed FMA), wi logits; xn stored =================
// grid = 256*4 = 1024, 512 threads, 4 row-blocks each
__global__ void __launch_bounds__(512,3) k_prep(const float* __restrict__ inp,
        const float* __restrict__ lng, const float* __restrict__ lnb,
        const float* __restrict__ Wk,
        const float* __restrict__ wiw, const float* __restrict__ wib){
  __shared__ float wkT[64*68];
  __shared__ float xsT[64*68];
  __shared__ float xrm[64*68];
  int blk=blockIdx.x;
  int b=blk>>2;
  int tid=threadIdx.x, w=tid>>5, l=tid&31;

  for(int e=tid;e<4096;e+=512){
    int j=e>>6, i=e&63;
    wkT[i*68+j]=Wk[e];
  }

  for(int bl=0;bl<4;bl++){
    int nb=((blk&3)*4+bl)*64;
    #pragma unroll
    for(int rr=0;rr<4;rr++){
      int row=w*4+rr;
      const float* xr=inp+(size_t)(b*1024+nb+row)*64;
      float x0=xr[l], x1=xr[l+32];
      float s1=wsum(x0+x1), s2=wsum(x0*x0+x1*x1);
      float m=s1*(1.f/64.f), var=s2*(1.f/64.f)-m*m;
      float rs=rsqrtf(var+1e-5f);
      float v0=(x0-m)*rs*lng[l]+lnb[l];
      float v1=(x1-m)*rs*lng[l+32]+lnb[l+32];
      xsT[l*68+row]=v0; xsT[(l+32)*68+row]=v1;
      xrm[row*68+l]=v0; xrm[row*68+l+32]=v1;
      float lp=wsum(v0*wiw[l]+v1*wiw[l+32]);
      if(l==0) g_logits[b*1024+nb+row]=lp+wib[0];
    }
    __syncthreads();

    // store xn coalesced
    #pragma unroll
    for(int q=0;q<8;q++){
      int o=tid+q*512;
      int n=o>>6, d=o&63;
      g_x[((size_t)(b*1024+nb+n))*64 + d]=xrm[n*68+d];
    }

    // k GEMM (packed), direct transposed store
    int rp=tid&31, j4=(tid>>5)*4;
    u64 kap[2][2]={{0,0},{0,0}};
    #pragma unroll 4
    for(int i=0;i<64;i++){
      float2 x2=*(const float2*)&xsT[i*68+rp*2];
      ulonglong2 wk=*(const ulonglong2*)&wkT[i*68+j4];
      u64 x0d=fdup(x2.x), x1d=fdup(x2.y);
      kap[0][0]=pfma(x0d,wk.x,kap[0][0]); kap[0][1]=pfma(x0d,wk.y,kap[0][1]);
      kap[1][0]=pfma(x1d,wk.x,kap[1][0]); kap[1][1]=pfma(x1d,wk.y,kap[1][1]);
    }
    float ka[2][4];
    #pragma unroll
    for(int r=0;r<2;r++){
      funpk(kap[r][0],ka[r][0],ka[r][1]); funpk(kap[r][1],ka[r][2],ka[r][3]);
    }
    {
      size_t kb=((size_t)b*64+j4)*1024 + nb + rp*2;
      #pragma unroll
      for(int jj=0;jj<4;jj++)
        *(float2*)&g_kT[kb + (size_t)jj*1024]=make_float2(ka[0][jj],ka[1][jj]);
    }
    __syncthreads();
  }
}

// ================= k_main: 256 threads, 4 n/thread; slot dim packed f32x2 =================
#define SO_UH  0       // 8192
#define SO_VT  8192    // 4096
#define SO_QS  12288   // 512 (qsT[d*8+s])
#define SO_SLT 12800   // 512
#define SO_UPD 13312   // 512
#define SO_EVH 13824   // 80
#define SO_EB  13904   // 8
#define SO_EBI 13912   // 8
#define SO_Q2  13920   // 8
#define SO_PS  13936   // 128 (double buffer 2x64, [vv*8+w])
#define SO_EVW 14064   // 64
#define SO_DVW 14128   // 64
#define SO_RED 14192   // 16
#define SM_TOT 14208
#define SMEM_BYTES (SM_TOT*4)

#define OUT_POS  131072
#define OUT_ATTN 135168

__global__ void __launch_bounds__(256,2) k_main(float* __restrict__ out,
  const float* __restrict__ noise, const float* __restrict__ mu, const float* __restrict__ sig,
  const float* __restrict__ Wq, const float* __restrict__ Wv,
  const float* __restrict__ lsg, const float* __restrict__ lsb,
  const float* __restrict__ wsw, const float* __restrict__ wsb,
  const float* __restrict__ wih, const float* __restrict__ whh,
  const float* __restrict__ bih, const float* __restrict__ bhh,
  const float* __restrict__ f1w, const float* __restrict__ f1b,
  const float* __restrict__ f2w, const float* __restrict__ f2b,
  const float* __restrict__ lfg, const float* __restrict__ lfb){
  extern __shared__ float sm[];
  float* UH  = sm + SO_UH;
  float* VT  = sm + SO_VT;
  float* qs  = sm + SO_QS;
  float* slt = sm + SO_SLT;
  float* upd = sm + SO_UPD;
  float* EVH = sm + SO_EVH;
  float* eb  = sm + SO_EB;
  float* ebi = sm + SO_EBI;
  float* q2  = sm + SO_Q2;
  float* ps  = sm + SO_PS;
  float* evw = sm + SO_EVW;
  float* dvw = sm + SO_DVW;
  float* red = sm + SO_RED;
  int b=blockIdx.x, tid=threadIdx.x, w=tid>>5, l=tid&31;
  int pbuf=0;
  int n0=2*tid;   // thread n-set: n0, n0+1, n0+512, n0+513
  const u64 ONEPK=0x3F8000003F800000ULL;

  // ---- slots init ----
  #pragma unroll
  for(int k=0;k<2;k++){
    int idx=tid+k*256; int d=idx&63;
    slt[idx]=mu[d]+(fabsf(sig[d])+1e-8f)*noise[b*512+idx];
  }

  // ---- a = softmax(logits)*8 + eps (registers) ----
  float a4[4], ia4[4];
  {
    const float* lg=g_logits+b*1024;
    float2 A=*(const float2*)&lg[n0];
    float2 Bv=*(const float2*)&lg[n0+512];
    float mx=fmaxf(fmaxf(A.x,A.y),fmaxf(Bv.x,Bv.y));
    mx=wmax(mx);
    if(l==0) red[w]=mx;
    __syncthreads();
    float M=-1e30f;
    #pragma unroll
    for(int i=0;i<8;i++) M=fmaxf(M,red[i]);
    float e00=__expf(A.x-M), e01=__expf(A.y-M);
    float e10=__expf(Bv.x-M), e11=__expf(Bv.y-M);
    float ss=wsum(e00+e01+e10+e11);
    if(l==0) ps[w]=ss;
    __syncthreads();
    float S=0.f;
    #pragma unroll
    for(int i=0;i<8;i++) S+=ps[i];
    float invS=8.f/S;
    a4[0]=e00*invS+1e-8f; a4[1]=e01*invS+1e-8f;
    a4[2]=e10*invS+1e-8f; a4[3]=e11*invS+1e-8f;
    #pragma unroll
    for(int i=0;i<4;i++) ia4[i]=rcpf(a4[i]);
  }
  __syncthreads();

  for(int itr=0;itr<3;itr++){
    int last=(itr==2);

    // ---- slotproj: LN(slots) -> UH[0..512), ws logits ----
    {
      float x0=slt[w*64+l], x1=slt[w*64+l+32];
      float s1=wsum(x0+x1), s2=wsum(x0*x0+x1*x1);
      float m=s1*(1.f/64.f), var=s2*(1.f/64.f)-m*m;
      float rs=rsqrtf(var+1e-5f);
      float nn0=(x0-m)*rs*lsg[l]+lsb[l];
      float nn1=(x1-m)*rs*lsg[l+32]+lsb[l+32];
      UH[w*64+l]=nn0; UH[w*64+l+32]=nn1;
      float lp=wsum(nn0*wsw[l]+nn1*wsw[l+32]);
      if(l==0) red[w]=lp+wsb[0];
    }
    __syncthreads();
    if(tid==0){
      float M=red[0];
      for(int i=1;i<8;i++) M=fmaxf(M,red[i]);
      float S=0.f;
      for(int i=0;i<8;i++) S+=__expf(red[i]-M);
      for(int i=0;i<8;i++){
        float bb=8.f*__expf(red[i]-M)/S+1e-8f;
        eb[i]=bb; ebi[i]=rcpf(bb);
      }
    }
    // ---- q projection (2 outputs/thread) -> qsT[d*8+s], |q|^2 ----
    {
      float qv[2]; int sidx[2], didx[2];
      #pragma unroll
      for(int k=0;k<2;k++){
        int idx=tid+k*256;
        int s=idx>>6, d=idx&63;
        sidx[k]=s; didx[k]=d;
        float q=0.f;
        const float4* wq4=(const float4*)(Wq+d*64);
        const float* sns=UH+s*64;
        #pragma unroll
        for(int i4=0;i4<16;i4++){
          float4 ww=wq4[i4];
          q=fmaf(sns[i4*4+0],ww.x,fmaf(sns[i4*4+1],ww.y,fmaf(sns[i4*4+2],ww.z,fmaf(sns[i4*4+3],ww.w,q))));
        }
        qv[k]=q;
        float pq=wsum(q*q);
        if(l==0) ps[k*8+w]=pq;
      }
      __syncthreads();
      qs[didx[0]*8+sidx[0]]=qv[0];
      qs[didx[1]*8+sidx[1]]=qv[1];
      if(tid<8){
        int base=(tid>>2)*8+(tid&3)*2;
        q2[tid]=ps[base]+ps[base+1];
      }
    }
    __syncthreads();

    // ---- cdist -> E packed in registers: Epk[g*4+j] = (E[g][2j], E[g][2j+1]) ----
    u64 Epk[16];
    {
      float q2r[8];
      #pragma unroll
      for(int s=0;s<8;s++) q2r[s]=q2[s];
      u64 dp[16];
      #pragma unroll
      for(int i=0;i<16;i++) dp[i]=0ULL;
      u64 k2p[2]={0ULL,0ULL};
      const float* kTb = g_kT + (size_t)b*65536;
      for(int d=0;d<64;d++){
        ulonglong2 qA=*(const ulonglong2*)&qs[d*8];
        ulonglong2 qB=*(const ulonglong2*)&qs[d*8+4];
        u64 qp[4]={qA.x,qA.y,qB.x,qB.y};
        float2 kA=*(const float2*)&kTb[d*1024 + n0];
        float2 kB=*(const float2*)&kTb[d*1024 + n0 + 512];
        u64 kApk=fpk(kA.x,kA.y), kBpk=fpk(kB.x,kB.y);
        k2p[0]=pfma(kApk,kApk,k2p[0]);
        k2p[1]=pfma(kBpk,kBpk,k2p[1]);
        float kv[4]={kA.x,kA.y,kB.x,kB.y};
        #pragma unroll
        for(int g=0;g<4;g++){
          u64 kd=fdup(kv[g]);
          dp[g*4+0]=pfma(kd,qp[0],dp[g*4+0]);
          dp[g*4+1]=pfma(kd,qp[1],dp[g*4+1]);
          dp[g*4+2]=pfma(kd,qp[2],dp[g*4+2]);
          dp[g*4+3]=pfma(kd,qp[3],dp[g*4+3]);
        }
      }
      float k2[4];
      funpk(k2p[0],k2[0],k2[1]);
      funpk(k2p[1],k2[2],k2[3]);
      #pragma unroll
      for(int g=0;g<4;g++)
        #pragma unroll
        for(int j=0;j<4;j++){
          float d0,d1; funpk(dp[g*4+j],d0,d1);
          float e0=__expf(-sqrtf(fmaxf(k2[g]+q2r[2*j]  -2.f*d0,1e-12f)));
          float e1=__expf(-sqrtf(fmaxf(k2[g]+q2r[2*j+1]-2.f*d1,1e-12f)));
          Epk[g*4+j]=fpk(e0,e1);
        }
    }
    __syncthreads();

    // packed 1/(b+eps), constant within this itr
    ulonglong2 biA=*(const ulonglong2*)&ebi[0];
    ulonglong2 biB=*(const ulonglong2*)&ebi[4];
    u64 bip[4]={biA.x,biA.y,biB.x,biB.y};

    // ---- MESH ----
    float du4[4]={0.f,0.f,0.f,0.f};
    float euL[4];
    for(int mesh=0;mesh<4;mesh++){
      if(tid<8) EVH[tid]=1.f;
      __syncthreads();
      // forward
      for(int t=0;t<8;t++){
        u64 evp[4];
        if(t==0){
          evp[0]=evp[1]=evp[2]=evp[3]=ONEPK;
        } else {
          ulonglong2 eA=*(const ulonglong2*)&evw[w*8];
          ulonglong2 eB=*(const ulonglong2*)&evw[w*8+4];
          evp[0]=eA.x; evp[1]=eA.y; evp[2]=eB.x; evp[3]=eB.y;
        }
        u64 colp[4]={0ULL,0ULL,0ULL,0ULL};
        float eu4[4];
        #pragma unroll
        for(int g=0;g<4;g++){
          u64 acc=fpk(1e-38f,0.f);
          acc=pfma(evp[0],Epk[g*4+0],acc);
          acc=pfma(evp[1],Epk[g*4+1],acc);
          acc=pfma(evp[2],Epk[g*4+2],acc);
          acc=pfma(evp[3],Epk[g*4+3],acc);
          float xa,xb; funpk(acc,xa,xb);
          float eu=a4[g]*rcpf(xa+xb);
          eu4[g]=eu;
          if(t==7) euL[g]=eu;
          u64 eup=fdup(eu);
          colp[0]=pfma(eup,Epk[g*4+0],colp[0]);
          colp[1]=pfma(eup,Epk[g*4+1],colp[1]);
          colp[2]=pfma(eup,Epk[g*4+2],colp[2]);
          colp[3]=pfma(eup,Epk[g*4+3],colp[3]);
        }
        *(float2*)&UH[t*1024+n0]    =make_float2(eu4[0],eu4[1]);
        *(float2*)&UH[t*1024+n0+512]=make_float2(eu4[2],eu4[3]);
        float colacc[8];
        funpk(colp[0],colacc[0],colacc[1]);
        funpk(colp[1],colacc[2],colacc[3]);
        funpk(colp[2],colacc[4],colacc[5]);
        funpk(colp[3],colacc[6],colacc[7]);
        float r3=mred8(colacc,l);
        float* pb=ps+(pbuf<<6);
        if(l<8) pb[br3(l)*8+w]=r3;
        __syncthreads();
        if(l<8){
          int vv=br3(l);
          float4 A=*(const float4*)&pb[vv*8];
          float4 Bv=*(const float4*)&pb[vv*8+4];
          float tot=A.x+A.y+A.z+A.w+Bv.x+Bv.y+Bv.z+Bv.w;
          float evv=eb[vv]*rcpf(tot+1e-38f);
          evw[w*8+vv]=evv;
          if(w==0) EVH[(t+1)*8+vv]=evv;
        }
        __syncwarp();
        pbuf^=1;
      }
      // entropy direct terms
      u64 Gpk[16];
      {
        float4 e0=*(const float4*)&evw[w*8];
        float4 e1=*(const float4*)&evw[w*8+4];
        float ev8[8]={e0.x,e0.y,e0.z,e0.w,e1.x,e1.y,e1.z,e1.w};
        float colacc[8];
        #pragma unroll
        for(int s=0;s<8;s++) colacc[s]=0.f;
        #pragma unroll
        for(int g=0;g<4;g++){
          float ra=0.f, eug=euL[g];
          #pragma unroll
          for(int j=0;j<4;j++){
            float E0,E1; funpk(Epk[g*4+j],E0,E1);
            float P0=eug*ev8[2*j]*E0,   P1=eug*ev8[2*j+1]*E1;
            float Pe0=P0+1e-8f,         Pe1=P1+1e-8f;
            float t00=P0*(__logf(Pe0)+P0*rcpf(Pe0));
            float t01=P1*(__logf(Pe1)+P1*rcpf(Pe1));
            Gpk[g*4+j]=fpk(t00,t01);
            ra+=t00+t01;
            colacc[2*j]+=t00; colacc[2*j+1]+=t01;
          }
          du4[g]=-ra;
        }
        float r3=mred8(colacc,l);
        float* pb=ps+(pbuf<<6);
        if(l<8) pb[br3(l)*8+w]=r3;
        __syncthreads();
        if(l<8){
          int vv=br3(l);
          float4 A=*(const float4*)&pb[vv*8];
          float4 Bv=*(const float4*)&pb[vv*8+4];
          dvw[w*8+vv]=-(A.x+A.y+A.z+A.w+Bv.x+Bv.y+Bv.z+Bv.w);
        }
        __syncwarp();
        pbuf^=1;
      }
      // backward t=7..0 (t=0 publishes nothing); EVH row t+1 carried in regs
      u64 hp[4];
      {
        ulonglong2 hA=*(const ulonglong2*)&EVH[64];
        ulonglong2 hB=*(const ulonglong2*)&EVH[68];
        hp[0]=hA.x; hp[1]=hA.y; hp[2]=hB.x; hp[3]=hB.y;
      }
      for(int t=7;t>=0;t--){
        ulonglong2 dA=*(const ulonglong2*)&dvw[w*8];
        ulonglong2 dB=*(const ulonglong2*)&dvw[w*8+4];
        u64 wp[4]={pmul(pmul(dA.x,hp[0]),bip[0]),
                   pmul(pmul(dA.y,hp[1]),bip[1]),
                   pmul(pmul(dB.x,hp[2]),bip[2]),
                   pmul(pmul(dB.y,hp[3]),bip[3])};
        ulonglong2 mA=*(const ulonglong2*)&EVH[t*8];
        ulonglong2 mB=*(const ulonglong2*)&EVH[t*8+4];
        u64 mpk[4]={mA.x,mA.y,mB.x,mB.y};
        float ut[4];
        if(t==7){
          ut[0]=euL[0]; ut[1]=euL[1]; ut[2]=euL[2]; ut[3]=euL[3];
        } else {
          float2 uA=*(const float2*)&UH[t*1024+n0];
          float2 uB=*(const float2*)&UH[t*1024+n0+512];
          ut[0]=uA.x; ut[1]=uA.y; ut[2]=uB.x; ut[3]=uB.y;
        }
        u64 colp[4]={0ULL,0ULL,0ULL,0ULL};
        #pragma unroll
        for(int g=0;g<4;g++){
          u64 t1p=0ULL;
          t1p=pfma(wp[0],Epk[g*4+0],t1p);
          t1p=pfma(wp[1],Epk[g*4+1],t1p);
          t1p=pfma(wp[2],Epk[g*4+2],t1p);
          t1p=pfma(wp[3],Epk[g*4+3],t1p);
          float ta,tb; funpk(t1p,ta,tb);
          float uacc=((t==7)?du4[g]:0.f)-ut[g]*(ta+tb);
          float fun=uacc*ut[g]*ia4[g];
          u64 fd=fdup(fun), ud=fdup(ut[g]);
          #pragma unroll
          for(int j=0;j<4;j++){
            u64 inner=pfma(ud,wp[j],pmul(fd,mpk[j]));
            Gpk[g*4+j]=pfma(Epk[g*4+j],inner,Gpk[g*4+j]);
            colp[j]=pfma(fd,Epk[g*4+j],colp[j]);
          }
        }
        if(t>0){
          float colacc[8];
          funpk(colp[0],colacc[0],colacc[1]);
          funpk(colp[1],colacc[2],colacc[3]);
          funpk(colp[2],colacc[4],colacc[5]);
          funpk(colp[3],colacc[6],colacc[7]);
          float r3=mred8(colacc,l);
          float* pb=ps+(pbuf<<6);
          if(l<8) pb[br3(l)*8+w]=r3;
          __syncthreads();
          if(l<8){
            int vv=br3(l);
            float4 A=*(const float4*)&pb[vv*8];
            float4 Bv=*(const float4*)&pb[vv*8+4];
            dvw[w*8+vv]=-EVH[t*8+vv]*(A.x+A.y+A.z+A.w+Bv.x+Bv.y+Bv.z+Bv.w);
          }
          __syncwarp();
          pbuf^=1;
        }
        hp[0]=mpk[0]; hp[1]=mpk[1]; hp[2]=mpk[2]; hp[3]=mpk[3];
      }
      // E *= exp(3*G) via packed pre-scale + ex2
      {
        const u64 C3L=fdup(3.0f*1.4426950408889634f);
        #pragma unroll
        for(int p=0;p<16;p++){
          u64 gl=pmul(Gpk[p],C3L);
          float g0,g1; funpk(gl,g0,g1);
          Epk[p]=pmul(Epk[p], fpk(ex2f(g0),ex2f(g1)));
        }
      }
    }

    // ---- final sinkhorn (warm exp(v)) ----
    for(int it=0;it<8;it++){
      u64 evp[4];
      if(it==0){
        ulonglong2 eA=*(const ulonglong2*)&EVH[64];
        ulonglong2 eB=*(const ulonglong2*)&EVH[68];
        evp[0]=eA.x; evp[1]=eA.y; evp[2]=eB.x; evp[3]=eB.y;
      } else {
        ulonglong2 eA=*(const ulonglong2*)&evw[w*8];
        ulonglong2 eB=*(const ulonglong2*)&evw[w*8+4];
        evp[0]=eA.x; evp[1]=eA.y; evp[2]=eB.x; evp[3]=eB.y;
      }
      u64 colp[4]={0ULL,0ULL,0ULL,0ULL};
      #pragma unroll
      for(int g=0;g<4;g++){
        u64 acc=fpk(1e-38f,0.f);
        acc=pfma(evp[0],Epk[g*4+0],acc);
        acc=pfma(evp[1],Epk[g*4+1],acc);
        acc=pfma(evp[2],Epk[g*4+2],acc);
        acc=pfma(evp[3],Epk[g*4+3],acc);
        float xa,xb; funpk(acc,xa,xb);
        float eu=a4[g]*rcpf(xa+xb);
        if(it==7) euL[g]=eu;
        u64 eup=fdup(eu);
        colp[0]=pfma(eup,Epk[g*4+0],colp[0]);
        colp[1]=pfma(eup,Epk[g*4+1],colp[1]);
        colp[2]=pfma(eup,Epk[g*4+2],colp[2]);
        colp[3]=pfma(eup,Epk[g*4+3],colp[3]);
      }
      float colacc[8];
      funpk(colp[0],colacc[0],colacc[1]);
      funpk(colp[1],colacc[2],colacc[3]);
      funpk(colp[2],colacc[4],colacc[5]);
      funpk(colp[3],colacc[6],colacc[7]);
      float r3=mred8(colacc,l);
      float* pb=ps+(pbuf<<6);
      if(l<8) pb[br3(l)*8+w]=r3;
      __syncthreads();
      if(l<8){
        int vv=br3(l);
        float4 A=*(const float4*)&pb[vv*8];
        float4 Bv=*(const float4*)&pb[vv*8+4];
        evw[w*8+vv]=eb[vv]*rcpf(A.x+A.y+A.z+A.w+Bv.x+Bv.y+Bv.z+Bv.w+1e-38f);
      }
      __syncwarp();
      pbuf^=1;
    }

    // ---- P = EU*EV*E -> UH (and attn out) ----
    {
      float4 e0=*(const float4*)&evw[w*8];
      float4 e1=*(const float4*)&evw[w*8+4];
      float evf[8]={e0.x,e0.y,e0.z,e0.w,e1.x,e1.y,e1.z,e1.w};
      #pragma unroll
      for(int j=0;j<4;j++){
        float E00,E01,E10,E11,E20,E21,E30,E31;
        funpk(Epk[0*4+j],E00,E01);
        funpk(Epk[1*4+j],E10,E11);
        funpk(Epk[2*4+j],E20,E21);
        funpk(Epk[3*4+j],E30,E31);
        int s0=2*j, s1=2*j+1;
        float2 PA0=make_float2(euL[0]*evf[s0]*E00, euL[1]*evf[s0]*E10);
        float2 PB0=make_float2(euL[2]*evf[s0]*E20, euL[3]*evf[s0]*E30);
        float2 PA1=make_float2(euL[0]*evf[s1]*E01, euL[1]*evf[s1]*E11);
        float2 PB1=make_float2(euL[2]*evf[s1]*E21, euL[3]*evf[s1]*E31);
        *(float2*)&UH[s0*1024+n0]    =PA0;
        *(float2*)&UH[s0*1024+n0+512]=PB0;
        *(float2*)&UH[s1*1024+n0]    =PA1;
        *(float2*)&UH[s1*1024+n0+512]=PB1;
        if(last){
          *(float2*)&out[OUT_ATTN+b*8192+s0*1024+n0]    =PA0;
          *(float2*)&out[OUT_ATTN+b*8192+s0*1024+n0+512]=PB0;
          *(float2*)&out[OUT_ATTN+b*8192+s1*1024+n0]    =PA1;
          *(float2*)&out[OUT_ATTN+b*8192+s1*1024+n0+512]=PB1;
        }
      }
    }
    __syncthreads();

    // ---- slot_pos (last): warp w -> slot w ----
    if(last){
      const float* Pp=UH+w*1024;
      float gx=0.f,gy=0.f;
      #pragma unroll 4
      for(int i=l;i<1024;i+=32){
        float p=Pp[i];
        gx=fmaf(p,(float)(i&31),gx);
        gy=fmaf(p,(float)(i>>5),gy);
      }
      gx=wsum(gx); gy=wsum(gy);
      if(l==0){
        out[OUT_POS+(b*8+w)*2+0]=gx*(1.f/31.f);
        out[OUT_POS+(b*8+w)*2+1]=gy*(1.f/31.f);
      }
    }

    // ---- PX = P @ xn : split-n, packed, thread -> (half h, s, d-quad) ----
    {
      int h=tid>>7, s=(tid>>4)&7, d4=(tid&15)*4;
      u64 ap0=0ULL, ap1=0ULL;
      const float4* gv4=(const float4*)(g_x+(size_t)b*65536);
      float4* VT4=(float4*)VT;
      for(int t16=0;t16<16;t16++){
        #pragma unroll
        for(int j=0;j<4;j++) VT4[tid+j*256]=gv4[t16*1024+tid+j*256];
        __syncthreads();
        const float* PA=UH+s*1024+t16*64+h*32;
        #pragma unroll 4
        for(int r=0;r<32;r+=2){
          float2 p2=*(const float2*)&PA[r];
          u64 pd0=fdup(p2.x), pd1=fdup(p2.y);
          ulonglong2 v0=*(const ulonglong2*)&VT[(h*32+r)*64+d4];
          ulonglong2 v1=*(const ulonglong2*)&VT[(h*32+r+1)*64+d4];
          ap0=pfma(pd0,v0.x,ap0); ap1=pfma(pd0,v0.y,ap1);
          ap0=pfma(pd1,v1.x,ap0); ap1=pfma(pd1,v1.y,ap1);
        }
        __syncthreads();
      }
      float o0,o1,o2,o3; funpk(ap0,o0,o1); funpk(ap1,o2,o3);
      float* dst = h ? qs : upd;
      *(float4*)&dst[s*64+d4]=make_float4(o0,o1,o2,o3);
    }
    __syncthreads();
    // combine halves: PX -> qs
    #pragma unroll
    for(int k=0;k<2;k++){ int idx=tid+k*256; qs[idx]=upd[idx]+qs[idx]; }
    __syncthreads();
    // ---- updates = PX @ Wv^T -> upd ----
    #pragma unroll
    for(int k=0;k<2;k++){
      int idx=tid+k*256;
      int s2=idx>>6, d=idx&63;
      u64 ap=0ULL;
      const ulonglong2* wv2=(const ulonglong2*)(Wv+d*64);
      const ulonglong2* px2=(const ulonglong2*)(qs+s2*64);
      #pragma unroll
      for(int i4=0;i4<16;i4++){
        ulonglong2 A=wv2[i4], X=px2[i4];
        ap=pfma(X.x,A.x,ap); ap=pfma(X.y,A.y,ap);
      }
      float ax,ay; funpk(ap,ax,ay);
      upd[idx]=ax+ay;
    }
    __syncthreads();

    // ---- GRU (scratch in UH), packed dot products ----
    #pragma unroll
    for(int k=0;k<6;k++){
      int idx=tid+k*256;
      int s2=idx/192, j=idx-s2*192;
      u64 ap=0ULL, cp=0ULL;
      const ulonglong2* w1=(const ulonglong2*)(wih+j*64);
      const ulonglong2* w2=(const ulonglong2*)(whh+j*64);
      const ulonglong2* us=(const ulonglong2*)(upd+s2*64);
      const ulonglong2* hs=(const ulonglong2*)(slt+s2*64);
      #pragma unroll
      for(int i4=0;i4<16;i4++){
        ulonglong2 A=w1[i4], Bm=w2[i4], U=us[i4], H=hs[i4];
        ap=pfma(U.x,A.x,ap); ap=pfma(U.y,A.y,ap);
        cp=pfma(H.x,Bm.x,cp); cp=pfma(H.y,Bm.y,cp);
      }
      float ax,ay,cx,cy; funpk(ap,ax,ay); funpk(cp,cx,cy);
      UH[idx]=ax+ay+bih[j]; UH[1536+idx]=cx+cy+bhh[j];
    }
    __syncthreads();
    #pragma unroll
    for(int k=0;k<2;k++){
      int idx=tid+k*256;
      int s2=idx>>6, d=idx&63;
      float r=sigf(UH[s2*192+d]+UH[1536+s2*192+d]);
      float z=sigf(UH[s2*192+64+d]+UH[1536+s2*192+64+d]);
      float nn=tanhf(UH[s2*192+128+d]+r*UH[1536+s2*192+128+d]);
      UH[3072+idx]=(1.f-z)*nn+z*slt[idx];
    }
    __syncthreads();
    // LN(ff)
    {
      float x0=UH[3072+w*64+l], x1=UH[3072+w*64+l+32];
      float s1=wsum(x0+x1), s2=wsum(x0*x0+x1*x1);
      float m=s1*(1.f/64.f), var=s2*(1.f/64.f)-m*m;
      float rs=rsqrtf(var+1e-5f);
      UH[3584+w*64+l]   =(x0-m)*rs*lfg[l]   +lfb[l];
      UH[3584+w*64+l+32]=(x1-m)*rs*lfg[l+32]+lfb[l+32];
    }
    __syncthreads();
    // fc1 (packed)
    #pragma unroll
    for(int k=0;k<4;k++){
      int idx=tid+k*256;
      int s2=idx>>7, j=idx&127;
      u64 ap=0ULL;
      const ulonglong2* w1=(const ulonglong2*)(f1w+j*64);
      const ulonglong2* xs=(const ulonglong2*)(UH+3584+s2*64);
      #pragma unroll
      for(int i4=0;i4<16;i4++){
        ulonglong2 A=w1[i4], X=xs[i4];
        ap=pfma(X.x,A.x,ap); ap=pfma(X.y,A.y,ap);
      }
      float ax,ay; funpk(ap,ax,ay);
      UH[4096+idx]=fmaxf(ax+ay+f1b[j],0.f);
    }
    __syncthreads();
    // fc2 + residual (packed)
    #pragma unroll
    for(int k=0;k<2;k++){
      int idx=tid+k*256;
      int s2=idx>>6, d=idx&63;
      u64 ap=0ULL;
      const ulonglong2* w2=(const ulonglong2*)(f2w+d*128);
      const ulonglong2* hs=(const ulonglong2*)(UH+4096+s2*128);
      #pragma unroll
      for(int i4=0;i4<32;i4++){
        ulonglong2 A=w2[i4], H=hs[i4];
        ap=pfma(H.x,A.x,ap); ap=pfma(H.y,A.y,ap);
      }
      float ax,ay; funpk(ap,ax,ay);
      float val=UH[3072+idx]+ax+ay+f2b[d];
      slt[idx]=val;
      if(last) out[b*512+idx]=val;
    }
    __syncthreads();
  }
}

extern "C" void kernel_launch(void* const* d_in, const int* in_sizes, int n_in,
                              void* d_out, int out_size){
  const float* inp  =(const float*)d_in[0];
  const float* noise=(const float*)d_in[1];
  const float* mu   =(const float*)d_in[2];
  const float* sig  =(const float*)d_in[3];
  const float* Wq   =(const float*)d_in[4];
  const float* Wk   =(const float*)d_in[5];
  const float* Wv   =(const float*)d_in[6];
  const float* wih  =(const float*)d_in[7];
  const float* whh  =(const float*)d_in[8];
  const float* bih  =(const float*)d_in[9];
  const float* bhh  =(const float*)d_in[10];
  const float* f1w  =(const float*)d_in[11];
  const float* f1b  =(const float*)d_in[12];
  const float* f2w  =(const float*)d_in[13];
  const float* f2b  =(const float*)d_in[14];
  const float* lig  =(const float*)d_in[15];
  const float* lib  =(const float*)d_in[16];
  const float* lsg  =(const float*)d_in[17];
  const float* lsb  =(const float*)d_in[18];
  const float* lfg  =(const float*)d_in[19];
  const float* lfb  =(const float*)d_in[20];
  const float* wiw  =(const float*)d_in[21];
  const float* wib  =(const float*)d_in[22];
  const float* wsw  =(const float*)d_in[23];
  const float* wsb  =(const float*)d_in[24];
  float* out=(float*)d_out;

  cudaFuncSetAttribute(k_main, cudaFuncAttributeMaxDynamicSharedMemorySize, SMEM_BYTES);

  k_prep<<<BB*4,512>>>(inp,lig,lib,Wk,wiw,wib);
  k_main<<<BB,256,SMEM_BYTES>>>(out,noise,mu,sig,Wq,Wv,lsg,lsb,wsw,wsb,
                                wih,whh,bih,bhh,f1w,f1b,f2w,f2b,lfg,lfb);
  (void)in_sizes; (void)n_in; (void)out_size;
}